// round 13
// baseline (speedup 1.0000x reference)
#include <cuda_runtime.h>
#include <cuda_fp16.h>
#include <math.h>
#include <stdint.h>

#define BB 2
#define NS 4
#define TT 2048
#define DD 1024
#define EE 16
#define NDIM 4096
#define DFFN 1656
#define LDP 1664
#define BT (BB*TT)
#define CAP BT
#define EPS_F 1.1920929e-7f
#define RSH 80
#define KC 64
#define STG_G 61440             // (256+128) rows x 160B
#define SMEM_G (2*STG_G)
#define STG_BF 61440
#define SMEM_F (2*STG_BF)

typedef __half hf;

// ---- device scratch ----
__device__ __align__(16) hf g_base[(size_t)BT*NDIM];
__device__ __align__(16) hf g_HN [(size_t)EE*CAP*DD];
__device__ __align__(16) hf g_T1 [(size_t)EE*CAP*DD];
__device__ __align__(16) hf g_P2 [(size_t)EE*CAP*LDP];
__device__ __align__(16) hf g_phiW[(size_t)EE*24*NDIM];
__device__ __align__(16) hf g_wd[(size_t)EE*DD*DD];
__device__ __align__(16) hf g_wu[(size_t)EE*DD*DD];
__device__ __align__(16) hf g_gt[(size_t)EE*DFFN*DD];
__device__ __align__(16) hf g_up[(size_t)EE*DFFN*DD];
__device__ __align__(16) hf g_dn[(size_t)EE*DD*LDP];
__device__ __align__(16) float g_GS [(size_t)EE*CAP*DD];
__device__ __align__(16) float g_OUT[(size_t)EE*CAP*DD];
__device__ __align__(16) float g_dots[(size_t)BT*384];
__device__ int   g_row[BT*EE];
__device__ float g_gatev[BT*EE];
__device__ int   g_cnt[EE];
__device__ int   g_tok[EE*CAP];
__device__ float g_Hpost[(size_t)EE*CAP*NS];
__device__ float g_Hres[(size_t)EE*CAP*16];

#define N1G 1048576L
#define N2G 1695744L
#define N3G 1703936L
#define NTOTG (2*N1G + 2*N2G + N3G)

// ---- helpers ----
__device__ __forceinline__ int posh(int n) {
    return ((n >> 1) & 3) * 4 + ((n >> 3) & 1) * 2 + (n & 1);
}
__device__ __forceinline__ void perm16(const float* s, __half2* o) {
    const int pr[8] = {0, 8, 2, 10, 4, 12, 6, 14};
    #pragma unroll
    for (int j = 0; j < 8; j++)
        o[j] = __floats2half2_rn(s[pr[j]], s[pr[j] + 1]);
}
__device__ __forceinline__ void mma16(float* c, uint32_t a0, uint32_t a1, uint32_t a2,
                                      uint32_t a3, uint32_t b0, uint32_t b1) {
    asm volatile(
        "mma.sync.aligned.m16n8k16.row.col.f32.f16.f16.f32 "
        "{%0,%1,%2,%3}, {%4,%5,%6,%7}, {%8,%9}, {%0,%1,%2,%3};"
        : "+f"(c[0]), "+f"(c[1]), "+f"(c[2]), "+f"(c[3])
        : "r"(a0), "r"(a1), "r"(a2), "r"(a3), "r"(b0), "r"(b1));
}
__device__ __forceinline__ void cp16(uint32_t s, const void* g, bool pr) {
    int b = pr ? 16 : 0;
    asm volatile("cp.async.cg.shared.global [%0], [%1], 16, %2;" :: "r"(s), "l"(g), "r"(b));
}

__global__ void k_zero() { if (threadIdx.x < EE) g_cnt[threadIdx.x] = 0; }

// ---- router gate + token rms + base emit (fused) ----
__global__ void __launch_bounds__(256) k_gate(const float* __restrict__ stream,
                                              const float* __restrict__ router_w,
                                              float* __restrict__ out_gate)
{
    int token = blockIdx.x, b = token / TT, t = token % TT, tid = threadIdx.x;
    __shared__ float route[DD], red[256], logit[EE];
    const float* sp0 = stream + ((size_t)b * NS * TT + t) * DD;
    float v[4][4];
    float ss = 0.f;
    #pragma unroll
    for (int it = 0; it < 4; it++) {
        int dd = tid + it * 256;
        float v0 = sp0[dd], v1 = sp0[(size_t)TT*DD + dd];
        float v2 = sp0[2*(size_t)TT*DD + dd], v3 = sp0[3*(size_t)TT*DD + dd];
        v[it][0] = v0; v[it][1] = v1; v[it][2] = v2; v[it][3] = v3;
        ss += v0*v0 + v1*v1 + v2*v2 + v3*v3;
        route[dd] = 0.25f * (v0 + v1 + v2 + v3);
    }
    red[tid] = ss; __syncthreads();
    for (int s = 128; s > 0; s >>= 1) { if (tid < s) red[tid] += red[tid+s]; __syncthreads(); }
    float srms = rsqrtf(red[0] / (float)NDIM + EPS_F);

    hf* dst = g_base + (size_t)token * NDIM;
    #pragma unroll
    for (int it = 0; it < 4; it++) {
        int dd = tid + it * 256;
        #pragma unroll
        for (int i = 0; i < 4; i++) {
            int j = i * 1024 + dd;
            dst[(j & ~15) | posh(j & 15)] = __float2half_rn(v[it][i] * srms);
        }
    }

    int warp = tid >> 5, lane = tid & 31;
    for (int e = warp; e < EE; e += 8) {
        const float* rw = router_w + (size_t)e * DD;
        float acc = 0.f;
        for (int dd = lane; dd < DD; dd += 32) acc += route[dd] * rw[dd];
        #pragma unroll
        for (int o = 16; o > 0; o >>= 1) acc += __shfl_down_sync(0xffffffffu, acc, o);
        if (lane == 0) logit[e] = acc;
    }
    __syncthreads();
    if (tid == 0) {
        float p[EE], mx = -1e30f;
        #pragma unroll
        for (int e = 0; e < EE; e++) mx = fmaxf(mx, logit[e]);
        float sum = 0.f;
        #pragma unroll
        for (int e = 0; e < EE; e++) { p[e] = expf(logit[e] - mx); sum += p[e]; }
        float inv = 1.f / sum;
        #pragma unroll
        for (int e = 0; e < EE; e++) p[e] *= inv;
        int ord[EE];
        #pragma unroll
        for (int e = 0; e < EE; e++) ord[e] = e;
        for (int i = 1; i < EE; i++) {
            int oi = ord[i]; float pi = p[oi]; int j = i - 1;
            while (j >= 0 && p[ord[j]] < pi) { ord[j+1] = ord[j]; j--; }
            ord[j+1] = oi;
        }
        float cum = 0.f, gate[EE];
        #pragma unroll
        for (int e = 0; e < EE; e++) gate[e] = 0.f;
        for (int r = 0; r < EE; r++) {
            int e = ord[r];
            if ((r == 0) || (cum < 0.8f && r < 4)) gate[e] = p[e];
            cum += p[e];
        }
        for (int e = 0; e < EE; e++) {
            float g = gate[e];
            out_gate[(size_t)token*EE + e] = g;
            g_gatev[token*EE + e] = g;
            int row = -1;
            if (g > 0.f) { row = atomicAdd(&g_cnt[e], 1); g_tok[e*CAP + row] = token; }
            g_row[token*EE + e] = row;
        }
    }
}

// ---- phi weights pack ----
__global__ void __launch_bounds__(256) k_pack(const float* __restrict__ mhc_norm_w,
                                              const float* __restrict__ pw,
                                              const float* __restrict__ ow,
                                              const float* __restrict__ rw)
{
    int g = blockIdx.x * 256 + threadIdx.x;
    int e = g / 6144;
    int rem = g - e * 6144;
    int r = rem >> 8;
    int j0 = (rem & 255) * 16;
    const float* wsrc;
    if (r < 4)      wsrc = pw + ((size_t)e*4 + r)*NDIM + j0;
    else if (r < 8) wsrc = ow + ((size_t)e*4 + (r-4))*NDIM + j0;
    else            wsrc = rw + ((size_t)e*16 + (r-8))*NDIM + j0;
    const float* nsrc = mhc_norm_w + (size_t)e*NDIM + j0;
    float sv[16];
    #pragma unroll
    for (int q = 0; q < 4; q++) {
        float4 w = *(const float4*)(wsrc + q*4);
        float4 n = *(const float4*)(nsrc + q*4);
        sv[q*4+0] = w.x*n.x; sv[q*4+1] = w.y*n.y; sv[q*4+2] = w.z*n.z; sv[q*4+3] = w.w*n.w;
    }
    __half2 o[8]; perm16(sv, o);
    hf* q = g_phiW + (size_t)g * 16;
    *(uint4*)q = *(uint4*)o;
    *(uint4*)(q + 8) = *(uint4*)(o + 4);
}

// ---- merged weight pack ----
__device__ __forceinline__ void packgrp(const float* p, hf* q) {
    float sv[16];
    #pragma unroll
    for (int c = 0; c < 4; c++) {
        float4 v = *(const float4*)(p + c*4);
        sv[c*4+0] = v.x; sv[c*4+1] = v.y; sv[c*4+2] = v.z; sv[c*4+3] = v.w;
    }
    __half2 o[8]; perm16(sv, o);
    *(uint4*)q = *(uint4*)o;
    *(uint4*)(q + 8) = *(uint4*)(o + 4);
}
__global__ void __launch_bounds__(256) k_packall(const float* __restrict__ wd_w,
                                                 const float* __restrict__ wu_w,
                                                 const float* __restrict__ gate_w,
                                                 const float* __restrict__ up_w,
                                                 const float* __restrict__ down_w)
{
    long g0 = (long)blockIdx.x * 256 + threadIdx.x;
    long stride = (long)gridDim.x * 256;
    for (long g = g0; g < NTOTG; g += stride) {
        if (g < 2*N1G) {
            long l = (g < N1G) ? g : g - N1G;
            const float* src = (g < N1G) ? wd_w : wu_w;
            hf* dst = (g < N1G) ? g_wd : g_wu;
            long row = l >> 6; int gi = (int)(l & 63);
            packgrp(src + row * DD + gi * 16, dst + l * 16);
        } else if (g < 2*N1G + 2*N2G) {
            long l = g - 2*N1G;
            const float* src = (l < N2G) ? gate_w : up_w;
            hf* dst = (l < N2G) ? g_gt : g_up;
            if (l >= N2G) l -= N2G;
            long row = l >> 6; int gi = (int)(l & 63);
            packgrp(src + row * DD + gi * 16, dst + l * 16);
        } else {
            long l = g - 2*N1G - 2*N2G;
            long row = l / 104; int gi = (int)(l - row * 104);
            hf* q = g_dn + l * 16;
            if (gi * 16 + 16 <= DFFN) {
                packgrp(down_w + row * DFFN + gi * 16, q);
            } else {
                float sv[16];
                #pragma unroll
                for (int j = 0; j < 16; j++) {
                    int k = gi * 16 + j;
                    sv[j] = (k < DFFN) ? down_w[row * DFFN + k] : 0.f;
                }
                __half2 o[8]; perm16(sv, o);
                *(uint4*)q = *(uint4*)o;
                *(uint4*)(q + 8) = *(uint4*)(o + 4);
            }
        }
    }
}

// ---- fp16 GEMM, 256x128 CTA tile, 512 threads ----
// MODE 0 raw->Cf, 1 silu->Ch(intl half), 2 sigm->Cf, 5 mulAux->Cf
template <int MODE>
__global__ void __launch_bounds__(512, 1) k_gemm(
    const hf* __restrict__ A, int lda,
    const hf* __restrict__ W, int ldw, int Ntot, int KT,
    float* __restrict__ Cf, hf* __restrict__ Ch, int ldc,
    const float* __restrict__ Aux, int ldaux, int cntOv)
{
    extern __shared__ hf smh[];
    int e = blockIdx.z;
    int cnt = (cntOv >= 0) ? cntOv : g_cnt[e];
    int m0 = blockIdx.x * 256;
    if (m0 >= cnt) return;
    int n0 = blockIdx.y * 128;

    A += (size_t)e * CAP * lda;
    W += (size_t)e * Ntot * ldw;
    size_t co = (size_t)e * CAP * ldc;
    if (Cf) Cf += co;
    if (Ch) Ch += co;
    if (Aux) Aux += (size_t)e * CAP * ldaux;

    uint32_t sb = (uint32_t)__cvta_generic_to_shared(smh);
    int tid = threadIdx.x, warp = tid >> 5, lane = tid & 31;
    int wm = warp >> 2, wn = warp & 3;       // 4m x 4n warps, warp tile 64m x 32n
    int qr = lane >> 2, qc = lane & 3;

    float acc[4][4][4];
    #pragma unroll
    for (int mt = 0; mt < 4; mt++)
        #pragma unroll
        for (int nt = 0; nt < 4; nt++)
            #pragma unroll
            for (int q = 0; q < 4; q++) acc[mt][nt][q] = 0.f;

    // A rows occupy smem rows [0,256), W rows [256,384)
    auto load_stage = [&](int kt, int stg) {
        int k0 = kt * KC;
        #pragma unroll
        for (int i = 0; i < 6; i++) {
            int f = tid + i*512, r = f >> 3, c = f & 7;
            const hf* gp; bool pr = true;
            if (r < 256) {
                int mr = m0 + r;
                pr = mr < CAP;
                gp = A + (size_t)mr * lda + k0 + c*8;
            } else {
                int nr = n0 + r - 256;
                pr = nr < Ntot;
                gp = pr ? (W + (size_t)nr * ldw + k0 + c*8) : W;
            }
            cp16(sb + stg*STG_G + r*160 + c*16, gp, pr);
        }
        asm volatile("cp.async.commit_group;");
    };

    load_stage(0, 0);

    for (int kt = 0; kt < KT; kt++) {
        if (kt + 1 < KT) load_stage(kt + 1, (kt + 1) & 1);
        if (kt + 1 < KT) asm volatile("cp.async.wait_group 1;");
        else             asm volatile("cp.async.wait_group 0;");
        __syncthreads();

        int stg = kt & 1;
        const hf* Asm = smh + stg * (STG_G/2);
        const hf* Bsm = Asm + 256*RSH;

        #pragma unroll
        for (int ks = 0; ks < 4; ks++) {
            int kb = ks * 16 + qc * 4;
            uint2 al[4], ah[4];
            #pragma unroll
            for (int mt = 0; mt < 4; mt++) {
                al[mt] = *(const uint2*)(Asm + (wm*64 + mt*16 + qr)*RSH + kb);
                ah[mt] = *(const uint2*)(Asm + (wm*64 + mt*16 + qr + 8)*RSH + kb);
            }
            #pragma unroll
            for (int nt = 0; nt < 4; nt++) {
                uint2 bb = *(const uint2*)(Bsm + (wn*32 + nt*8 + qr)*RSH + kb);
                #pragma unroll
                for (int mt = 0; mt < 4; mt++)
                    mma16(acc[mt][nt], al[mt].x, ah[mt].x, al[mt].y, ah[mt].y, bb.x, bb.y);
            }
        }
        __syncthreads();
    }

    #pragma unroll
    for (int mt = 0; mt < 4; mt++) {
        #pragma unroll
        for (int nt = 0; nt < 4; nt++) {
            int n = n0 + wn*32 + nt*8 + qc*2;
            #pragma unroll
            for (int half = 0; half < 2; half++) {
                int m = m0 + wm*64 + mt*16 + qr + half*8;
                if (m >= cnt) continue;
                float v0 = acc[mt][nt][half*2], v1 = acc[mt][nt][half*2 + 1];
                if (MODE == 0) {
                    if (n < Ntot) {
                        float2 s2 = {v0, v1};
                        *(float2*)(Cf + (size_t)m * ldc + n) = s2;
                    }
                } else if (MODE == 2) {
                    if (n < Ntot) {
                        float2 s2 = {1.f/(1.f+expf(-v0)), 1.f/(1.f+expf(-v1))};
                        *(float2*)(Cf + (size_t)m * ldc + n) = s2;
                    }
                } else if (MODE == 5) {
                    if (n < Ntot) {
                        float2 s2 = {v0 * Aux[(size_t)m*ldaux + n], v1 * Aux[(size_t)m*ldaux + n + 1]};
                        *(float2*)(Cf + (size_t)m * ldc + n) = s2;
                    }
                } else {
                    if (n < Ntot) {
                        float x0 = v0/(1.f+expf(-v0)), x1 = v1/(1.f+expf(-v1));
                        size_t rowo = (size_t)m * ldc + (n & ~15);
                        *(__half2*)(Ch + rowo + posh(n & 15)) = __floats2half2_rn(x0, x1);
                    }
                }
            }
        }
    }
}

// ---- fused gate/up fp16 GEMM (unchanged) ----
__global__ void __launch_bounds__(512, 1) k_gemmF(
    const hf* __restrict__ A,
    const hf* __restrict__ Wg, const hf* __restrict__ Wu,
    hf* __restrict__ Ch)
{
    extern __shared__ hf smh[];
    int e = blockIdx.z;
    int cnt = g_cnt[e];
    int m0 = blockIdx.x * 128;
    if (m0 >= cnt) return;
    int n0 = blockIdx.y * 128;

    A  += (size_t)e * CAP * DD;
    Wg += (size_t)e * DFFN * DD;
    Wu += (size_t)e * DFFN * DD;
    Ch += (size_t)e * CAP * LDP;

    uint32_t sb = (uint32_t)__cvta_generic_to_shared(smh);
    int tid = threadIdx.x, warp = tid >> 5, lane = tid & 31;
    int wm = warp >> 3, wn = warp & 7;
    int qr = lane >> 2, qc = lane & 3;

    float accG[4][2][4], accU[4][2][4];
    #pragma unroll
    for (int mt = 0; mt < 4; mt++)
        #pragma unroll
        for (int nt = 0; nt < 2; nt++)
            #pragma unroll
            for (int q = 0; q < 4; q++) { accG[mt][nt][q] = 0.f; accU[mt][nt][q] = 0.f; }

    auto load_stage = [&](int kt, int stg) {
        int k0 = kt * KC;
        #pragma unroll
        for (int i = 0; i < 6; i++) {
            int f = tid + i*512, r = f >> 3, c = f & 7;
            const hf* gp; bool pr = true;
            if (r < 128) {
                gp = A + (size_t)(m0 + r)*DD + k0 + c*8;
            } else if (r < 256) {
                int nr = n0 + r - 128; pr = nr < DFFN;
                gp = pr ? (Wg + (size_t)nr*DD + k0 + c*8) : A;
            } else {
                int nr = n0 + r - 256; pr = nr < DFFN;
                gp = pr ? (Wu + (size_t)nr*DD + k0 + c*8) : A;
            }
            cp16(sb + stg*STG_BF + r*160 + c*16, gp, pr);
        }
        asm volatile("cp.async.commit_group;");
    };

    const int KT = DD / KC;
    load_stage(0, 0);

    for (int kt = 0; kt < KT; kt++) {
        if (kt + 1 < KT) load_stage(kt + 1, (kt + 1) & 1);
        if (kt + 1 < KT) asm volatile("cp.async.wait_group 1;");
        else             asm volatile("cp.async.wait_group 0;");
        __syncthreads();

        int stg = kt & 1;
        const hf* Asm = smh + stg * (STG_BF/2);
        const hf* Gsm = Asm + 10240;
        const hf* Usm = Asm + 20480;

        #pragma unroll
        for (int ks = 0; ks < 4; ks++) {
            int kb = ks * 16 + qc * 4;
            uint2 al[4], ah[4];
            #pragma unroll
            for (int mt = 0; mt < 4; mt++) {
                al[mt] = *(const uint2*)(Asm + (wm*64 + mt*16 + qr)*RSH + kb);
                ah[mt] = *(const uint2*)(Asm + (wm*64 + mt*16 + qr + 8)*RSH + kb);
            }
            #pragma unroll
            for (int nt = 0; nt < 2; nt++) {
                int br = (wn*16 + nt*8 + qr)*RSH + kb;
                uint2 bg = *(const uint2*)(Gsm + br);
                uint2 bu = *(const uint2*)(Usm + br);
                #pragma unroll
                for (int mt = 0; mt < 4; mt++) {
                    mma16(accG[mt][nt], al[mt].x, ah[mt].x, al[mt].y, ah[mt].y, bg.x, bg.y);
                    mma16(accU[mt][nt], al[mt].x, ah[mt].x, al[mt].y, ah[mt].y, bu.x, bu.y);
                }
            }
        }
        __syncthreads();
    }

    #pragma unroll
    for (int mt = 0; mt < 4; mt++) {
        #pragma unroll
        for (int nt = 0; nt < 2; nt++) {
            int n = n0 + wn*16 + nt*8 + qc*2;
            #pragma unroll
            for (int half = 0; half < 2; half++) {
                int m = m0 + wm*64 + mt*16 + qr + half*8;
                if (m >= cnt) continue;
                size_t rowo = (size_t)m * LDP + (n & ~15);
                int p0 = posh(n & 15);
                if (n < DFFN) {
                    float gv0 = accG[mt][nt][half*2], gv1 = accG[mt][nt][half*2 + 1];
                    float uv0 = accU[mt][nt][half*2], uv1 = accU[mt][nt][half*2 + 1];
                    float x0 = (gv0/(1.f+expf(-gv0))) * uv0;
                    float x1 = (gv1/(1.f+expf(-gv1))) * uv1;
                    *(__half2*)(Ch + rowo + p0) = __floats2half2_rn(x0, x1);
                } else if (n < LDP) {
                    *(__half2*)(Ch + rowo + p0) = __floats2half2_rn(0.f, 0.f);
                }
            }
        }
    }
}

// ---- per-token: gates, sinkhorn, h, hn ----
__global__ void __launch_bounds__(128) k_hn(const float* __restrict__ stream,
                                            const float* __restrict__ b_pre,
                                            const float* __restrict__ b_post,
                                            const float* __restrict__ b_res,
                                            const float* __restrict__ alpha_pre,
                                            const float* __restrict__ alpha_post,
                                            const float* __restrict__ alpha_res,
                                            const float* __restrict__ sw_norm_w)
{
    int token = blockIdx.x, b = token / TT, t = token % TT, tid = threadIdx.x;
    __shared__ float hpre[NS], red2[4];
    int lane = tid & 31, warp = tid >> 5;

    const float* sp0 = stream + ((size_t)b*NS*TT + t) * DD;
    float st[4][8];
    #pragma unroll
    for (int i = 0; i < 4; i++)
        #pragma unroll
        for (int u = 0; u < 8; u++)
            st[i][u] = sp0[(size_t)i*TT*DD + tid + u*128];

    for (int e = 0; e < EE; e++) {
        int row = g_row[token*EE + e];
        if (row < 0) continue;
        __syncthreads();
        if (tid == 0) {
            const float* d = g_dots + (size_t)token*384 + e*24;
            size_t slot = (size_t)e*CAP + row;
            float ap = alpha_pre[e], ao = alpha_post[e], ar = alpha_res[e];
            #pragma unroll
            for (int i = 0; i < NS; i++)
                hpre[i] = 1.f / (1.f + expf(-(ap*d[i] + b_pre[e*NS+i])));
            #pragma unroll
            for (int i = 0; i < NS; i++)
                g_Hpost[slot*NS+i] = 2.f / (1.f + expf(-(ao*d[4+i] + b_post[e*NS+i])));
            float M[16];
            #pragma unroll
            for (int k = 0; k < 16; k++) M[k] = expf(ar*d[8+k] + b_res[e*16+k]);
            for (int it = 0; it < 6; it++) {
                #pragma unroll
                for (int i = 0; i < 4; i++) {
                    float ir = 1.f / (M[i*4]+M[i*4+1]+M[i*4+2]+M[i*4+3]);
                    M[i*4]*=ir; M[i*4+1]*=ir; M[i*4+2]*=ir; M[i*4+3]*=ir;
                }
                #pragma unroll
                for (int j = 0; j < 4; j++) {
                    float ic = 1.f / (M[j]+M[4+j]+M[8+j]+M[12+j]);
                    M[j]*=ic; M[4+j]*=ic; M[8+j]*=ic; M[12+j]*=ic;
                }
            }
            #pragma unroll
            for (int k = 0; k < 16; k++) g_Hres[slot*16+k] = M[k];
        }
        __syncthreads();

        float h0 = hpre[0], h1 = hpre[1], h2 = hpre[2], h3 = hpre[3];
        float hreg[8], hq = 0.f;
        #pragma unroll
        for (int u = 0; u < 8; u++) {
            float h = h0*st[0][u] + h1*st[1][u] + h2*st[2][u] + h3*st[3][u];
            hreg[u] = h; hq += h*h;
        }
        #pragma unroll
        for (int o = 16; o > 0; o >>= 1) hq += __shfl_down_sync(0xffffffffu, hq, o);
        if (lane == 0) red2[warp] = hq;
        __syncthreads();
        float sh = rsqrtf((red2[0]+red2[1]+red2[2]+red2[3]) / (float)DD + EPS_F);
        const float* snw = sw_norm_w + (size_t)e*DD;
        hf* hn = g_HN + ((size_t)e*CAP + row) * DD;
        #pragma unroll
        for (int u = 0; u < 8; u++) {
            int dd = tid + u*128;
            float v = hreg[u] * sh * snw[dd];
            hn[(dd & ~15) + posh(dd & 15)] = __float2half_rn(v);
        }
    }
}

// ---- combine res + post ----
__global__ void __launch_bounds__(128) k_out(const float* __restrict__ stream,
                                             float* __restrict__ outp)
{
    int token = blockIdx.x, b = token / TT, t = token % TT, tid = threadIdx.x;
    const float* sp0 = stream + ((size_t)b*NS*TT + t) * DD;
    float st[4][8], acc[4][8];
    #pragma unroll
    for (int i = 0; i < 4; i++)
        #pragma unroll
        for (int j = 0; j < 8; j++) {
            st[i][j] = sp0[(size_t)i*TT*DD + tid + j*128];
            acc[i][j] = 0.f;
        }
    for (int e = 0; e < EE; e++) {
        int row = g_row[token*EE + e];
        if (row < 0) continue;
        float g = g_gatev[token*EE + e];
        size_t slot = (size_t)e*CAP + row;
        float Hr[16], Hp[4];
        #pragma unroll
        for (int k = 0; k < 16; k++) Hr[k] = g_Hres[slot*16+k];
        #pragma unroll
        for (int i = 0; i < 4; i++) Hp[i] = g_Hpost[slot*4+i];
        const float* o = g_OUT + slot*DD;
        #pragma unroll
        for (int j = 0; j < 8; j++) {
            float ov = o[tid + j*128];
            #pragma unroll
            for (int i = 0; i < 4; i++) {
                float r = Hr[i*4]*st[0][j] + Hr[i*4+1]*st[1][j]
                        + Hr[i*4+2]*st[2][j] + Hr[i*4+3]*st[3][j];
                acc[i][j] += g * (r + Hp[i]*ov);
            }
        }
    }
    #pragma unroll
    for (int i = 0; i < 4; i++)
        #pragma unroll
        for (int j = 0; j < 8; j++)
            outp[((size_t)(b*NS+i)*TT + t)*DD + tid + j*128] = acc[i][j];
}

#define GSA(p, s) cudaGetSymbolAddress((void**)&p, s)

extern "C" void kernel_launch(void* const* d_in, const int* in_sizes, int n_in,
                              void* d_out, int out_size)
{
    (void)in_sizes; (void)n_in; (void)out_size;
    const float* stream   = (const float*)d_in[0];
    const float* router_w = (const float*)d_in[1];
    const float* mhc      = (const float*)d_in[2];
    const float* phi_pre  = (const float*)d_in[3];
    const float* phi_post = (const float*)d_in[4];
    const float* phi_res  = (const float*)d_in[5];
    const float* b_pre    = (const float*)d_in[6];
    const float* b_post   = (const float*)d_in[7];
    const float* b_res    = (const float*)d_in[8];
    const float* a_pre    = (const float*)d_in[9];
    const float* a_post   = (const float*)d_in[10];
    const float* a_res    = (const float*)d_in[11];
    const float* sw_nw    = (const float*)d_in[12];
    const float* wd_w     = (const float*)d_in[13];
    const float* wu_w     = (const float*)d_in[14];
    const float* gate_w   = (const float*)d_in[15];
    const float* up_w     = (const float*)d_in[16];
    const float* down_w   = (const float*)d_in[17];

    float* outp = (float*)d_out;
    float* out_gate = outp + (size_t)BB*NS*TT*DD;

    cudaFuncSetAttribute(k_gemm<0>, cudaFuncAttributeMaxDynamicSharedMemorySize, SMEM_G);
    cudaFuncSetAttribute(k_gemm<1>, cudaFuncAttributeMaxDynamicSharedMemorySize, SMEM_G);
    cudaFuncSetAttribute(k_gemm<2>, cudaFuncAttributeMaxDynamicSharedMemorySize, SMEM_G);
    cudaFuncSetAttribute(k_gemm<5>, cudaFuncAttributeMaxDynamicSharedMemorySize, SMEM_G);
    cudaFuncSetAttribute(k_gemmF, cudaFuncAttributeMaxDynamicSharedMemorySize, SMEM_F);

    hf *base, *HN, *T1, *P2, *phiW, *gt, *up, *dn, *wd, *wu;
    float *GS, *OUT, *dots;
    GSA(base, g_base); GSA(HN, g_HN); GSA(T1, g_T1); GSA(P2, g_P2);
    GSA(phiW, g_phiW); GSA(wd, g_wd); GSA(wu, g_wu); GSA(gt, g_gt);
    GSA(up, g_up); GSA(dn, g_dn);
    GSA(GS, g_GS); GSA(OUT, g_OUT); GSA(dots, g_dots);

    k_zero<<<1, 32>>>();
    k_gate<<<BT, 256>>>(stream, router_w, out_gate);
    k_pack<<<(EE*24*NDIM/16)/256, 256>>>(mhc, phi_pre, phi_post, phi_res);
    k_packall<<<4096, 256>>>(wd_w, wu_w, gate_w, up_w, down_w);

    // dots = base @ phiW^T  (N=384, K=4096)
    k_gemm<0><<<dim3(16,3,1), 512, SMEM_G>>>(base, NDIM, phiW, NDIM, 384, NDIM/KC,
                                             dots, (hf*)0, 384, (const float*)0, 0, BT);

    k_hn<<<BT, 128>>>(stream, b_pre, b_post, b_res, a_pre, a_post, a_res, sw_nw);

    dim3 gD(16, 8, EE);

    // T1 = silu(HN @ wd^T) -> interleaved half
    k_gemm<1><<<gD, 512, SMEM_G>>>(HN, DD, wd, DD, DD, DD/KC,
                                   (float*)0, T1, DD, (const float*)0, 0, -1);
    // GS = sigmoid(T1 @ wu^T) -> f32
    k_gemm<2><<<gD, 512, SMEM_G>>>(T1, DD, wu, DD, DD, DD/KC,
                                   GS, (hf*)0, DD, (const float*)0, 0, -1);
    // P2 = silu(HN @ gt^T) * (HN @ up^T) -> interleaved half
    k_gemmF<<<dim3(32,13,EE), 512, SMEM_F>>>(HN, gt, up, P2);
    // OUT = (P2 @ dn^T) * GS -> f32
    k_gemm<5><<<gD, 512, SMEM_G>>>(P2, LDP, dn, LDP, DD, LDP/KC,
                                   OUT, (hf*)0, DD, GS, DD, -1);

    k_out<<<BT, 128>>>(stream, outp);
}

// round 14
// speedup vs baseline: 1.0455x; 1.0455x over previous
#include <cuda_runtime.h>
#include <cuda_fp16.h>
#include <math.h>
#include <stdint.h>

#define BB 2
#define NS 4
#define TT 2048
#define DD 1024
#define EE 16
#define NDIM 4096
#define DFFN 1656
#define LDP 1664
#define BT (BB*TT)
#define CAP BT
#define EPS_F 1.1920929e-7f
#define RSH 80
#define KC 64
#define STG_B 40960
#define SMEM_DYN (2*STG_B)
#define STG_BF 61440
#define SMEM_F (3*STG_BF)        // 3-stage pipeline for gemmF (184320 B)

typedef __half hf;

// ---- device scratch ----
__device__ __align__(16) hf g_base[(size_t)BT*NDIM];
__device__ __align__(16) hf g_HN [(size_t)EE*CAP*DD];
__device__ __align__(16) hf g_T1 [(size_t)EE*CAP*DD];
__device__ __align__(16) hf g_P2 [(size_t)EE*CAP*LDP];
__device__ __align__(16) hf g_phiW[(size_t)EE*24*NDIM];
__device__ __align__(16) hf g_wd[(size_t)EE*DD*DD];
__device__ __align__(16) hf g_wu[(size_t)EE*DD*DD];
__device__ __align__(16) hf g_gt[(size_t)EE*DFFN*DD];
__device__ __align__(16) hf g_up[(size_t)EE*DFFN*DD];
__device__ __align__(16) hf g_dn[(size_t)EE*DD*LDP];
__device__ __align__(16) float g_GS [(size_t)EE*CAP*DD];
__device__ __align__(16) float g_OUT[(size_t)EE*CAP*DD];
__device__ __align__(16) float g_dots[(size_t)BT*384];
__device__ int   g_row[BT*EE];
__device__ float g_gatev[BT*EE];
__device__ int   g_cnt[EE];
__device__ int   g_tok[EE*CAP];
__device__ float g_Hpost[(size_t)EE*CAP*NS];
__device__ float g_Hres[(size_t)EE*CAP*16];

#define N1G 1048576L
#define N2G 1695744L
#define N3G 1703936L
#define NTOTG (2*N1G + 2*N2G + N3G)

// ---- helpers ----
__device__ __forceinline__ int posh(int n) {
    return ((n >> 1) & 3) * 4 + ((n >> 3) & 1) * 2 + (n & 1);
}
__device__ __forceinline__ void perm16(const float* s, __half2* o) {
    const int pr[8] = {0, 8, 2, 10, 4, 12, 6, 14};
    #pragma unroll
    for (int j = 0; j < 8; j++)
        o[j] = __floats2half2_rn(s[pr[j]], s[pr[j] + 1]);
}
__device__ __forceinline__ void mma16(float* c, uint32_t a0, uint32_t a1, uint32_t a2,
                                      uint32_t a3, uint32_t b0, uint32_t b1) {
    asm volatile(
        "mma.sync.aligned.m16n8k16.row.col.f32.f16.f16.f32 "
        "{%0,%1,%2,%3}, {%4,%5,%6,%7}, {%8,%9}, {%0,%1,%2,%3};"
        : "+f"(c[0]), "+f"(c[1]), "+f"(c[2]), "+f"(c[3])
        : "r"(a0), "r"(a1), "r"(a2), "r"(a3), "r"(b0), "r"(b1));
}
__device__ __forceinline__ void cp16(uint32_t s, const void* g, bool pr) {
    int b = pr ? 16 : 0;
    asm volatile("cp.async.cg.shared.global [%0], [%1], 16, %2;" :: "r"(s), "l"(g), "r"(b));
}

__global__ void k_zero() { if (threadIdx.x < EE) g_cnt[threadIdx.x] = 0; }

// ---- router gate + token rms + base emit (fused) ----
__global__ void __launch_bounds__(256) k_gate(const float* __restrict__ stream,
                                              const float* __restrict__ router_w,
                                              float* __restrict__ out_gate)
{
    int token = blockIdx.x, b = token / TT, t = token % TT, tid = threadIdx.x;
    __shared__ float route[DD], red[256], logit[EE];
    const float* sp0 = stream + ((size_t)b * NS * TT + t) * DD;
    float v[4][4];
    float ss = 0.f;
    #pragma unroll
    for (int it = 0; it < 4; it++) {
        int dd = tid + it * 256;
        float v0 = sp0[dd], v1 = sp0[(size_t)TT*DD + dd];
        float v2 = sp0[2*(size_t)TT*DD + dd], v3 = sp0[3*(size_t)TT*DD + dd];
        v[it][0] = v0; v[it][1] = v1; v[it][2] = v2; v[it][3] = v3;
        ss += v0*v0 + v1*v1 + v2*v2 + v3*v3;
        route[dd] = 0.25f * (v0 + v1 + v2 + v3);
    }
    red[tid] = ss; __syncthreads();
    for (int s = 128; s > 0; s >>= 1) { if (tid < s) red[tid] += red[tid+s]; __syncthreads(); }
    float srms = rsqrtf(red[0] / (float)NDIM + EPS_F);

    hf* dst = g_base + (size_t)token * NDIM;
    #pragma unroll
    for (int it = 0; it < 4; it++) {
        int dd = tid + it * 256;
        #pragma unroll
        for (int i = 0; i < 4; i++) {
            int j = i * 1024 + dd;
            dst[(j & ~15) | posh(j & 15)] = __float2half_rn(v[it][i] * srms);
        }
    }

    int warp = tid >> 5, lane = tid & 31;
    for (int e = warp; e < EE; e += 8) {
        const float* rw = router_w + (size_t)e * DD;
        float acc = 0.f;
        for (int dd = lane; dd < DD; dd += 32) acc += route[dd] * rw[dd];
        #pragma unroll
        for (int o = 16; o > 0; o >>= 1) acc += __shfl_down_sync(0xffffffffu, acc, o);
        if (lane == 0) logit[e] = acc;
    }
    __syncthreads();
    if (tid == 0) {
        float p[EE], mx = -1e30f;
        #pragma unroll
        for (int e = 0; e < EE; e++) mx = fmaxf(mx, logit[e]);
        float sum = 0.f;
        #pragma unroll
        for (int e = 0; e < EE; e++) { p[e] = expf(logit[e] - mx); sum += p[e]; }
        float inv = 1.f / sum;
        #pragma unroll
        for (int e = 0; e < EE; e++) p[e] *= inv;
        int ord[EE];
        #pragma unroll
        for (int e = 0; e < EE; e++) ord[e] = e;
        for (int i = 1; i < EE; i++) {
            int oi = ord[i]; float pi = p[oi]; int j = i - 1;
            while (j >= 0 && p[ord[j]] < pi) { ord[j+1] = ord[j]; j--; }
            ord[j+1] = oi;
        }
        float cum = 0.f, gate[EE];
        #pragma unroll
        for (int e = 0; e < EE; e++) gate[e] = 0.f;
        for (int r = 0; r < EE; r++) {
            int e = ord[r];
            if ((r == 0) || (cum < 0.8f && r < 4)) gate[e] = p[e];
            cum += p[e];
        }
        for (int e = 0; e < EE; e++) {
            float g = gate[e];
            out_gate[(size_t)token*EE + e] = g;
            g_gatev[token*EE + e] = g;
            int row = -1;
            if (g > 0.f) { row = atomicAdd(&g_cnt[e], 1); g_tok[e*CAP + row] = token; }
            g_row[token*EE + e] = row;
        }
    }
}

// ---- phi weights pack ----
__global__ void __launch_bounds__(256) k_pack(const float* __restrict__ mhc_norm_w,
                                              const float* __restrict__ pw,
                                              const float* __restrict__ ow,
                                              const float* __restrict__ rw)
{
    int g = blockIdx.x * 256 + threadIdx.x;
    int e = g / 6144;
    int rem = g - e * 6144;
    int r = rem >> 8;
    int j0 = (rem & 255) * 16;
    const float* wsrc;
    if (r < 4)      wsrc = pw + ((size_t)e*4 + r)*NDIM + j0;
    else if (r < 8) wsrc = ow + ((size_t)e*4 + (r-4))*NDIM + j0;
    else            wsrc = rw + ((size_t)e*16 + (r-8))*NDIM + j0;
    const float* nsrc = mhc_norm_w + (size_t)e*NDIM + j0;
    float sv[16];
    #pragma unroll
    for (int q = 0; q < 4; q++) {
        float4 w = *(const float4*)(wsrc + q*4);
        float4 n = *(const float4*)(nsrc + q*4);
        sv[q*4+0] = w.x*n.x; sv[q*4+1] = w.y*n.y; sv[q*4+2] = w.z*n.z; sv[q*4+3] = w.w*n.w;
    }
    __half2 o[8]; perm16(sv, o);
    hf* q = g_phiW + (size_t)g * 16;
    *(uint4*)q = *(uint4*)o;
    *(uint4*)(q + 8) = *(uint4*)(o + 4);
}

// ---- merged weight pack ----
__device__ __forceinline__ void packgrp(const float* p, hf* q) {
    float sv[16];
    #pragma unroll
    for (int c = 0; c < 4; c++) {
        float4 v = *(const float4*)(p + c*4);
        sv[c*4+0] = v.x; sv[c*4+1] = v.y; sv[c*4+2] = v.z; sv[c*4+3] = v.w;
    }
    __half2 o[8]; perm16(sv, o);
    *(uint4*)q = *(uint4*)o;
    *(uint4*)(q + 8) = *(uint4*)(o + 4);
}
__global__ void __launch_bounds__(256) k_packall(const float* __restrict__ wd_w,
                                                 const float* __restrict__ wu_w,
                                                 const float* __restrict__ gate_w,
                                                 const float* __restrict__ up_w,
                                                 const float* __restrict__ down_w)
{
    long g0 = (long)blockIdx.x * 256 + threadIdx.x;
    long stride = (long)gridDim.x * 256;
    for (long g = g0; g < NTOTG; g += stride) {
        if (g < 2*N1G) {
            long l = (g < N1G) ? g : g - N1G;
            const float* src = (g < N1G) ? wd_w : wu_w;
            hf* dst = (g < N1G) ? g_wd : g_wu;
            long row = l >> 6; int gi = (int)(l & 63);
            packgrp(src + row * DD + gi * 16, dst + l * 16);
        } else if (g < 2*N1G + 2*N2G) {
            long l = g - 2*N1G;
            const float* src = (l < N2G) ? gate_w : up_w;
            hf* dst = (l < N2G) ? g_gt : g_up;
            if (l >= N2G) l -= N2G;
            long row = l >> 6; int gi = (int)(l & 63);
            packgrp(src + row * DD + gi * 16, dst + l * 16);
        } else {
            long l = g - 2*N1G - 2*N2G;
            long row = l / 104; int gi = (int)(l - row * 104);
            hf* q = g_dn + l * 16;
            if (gi * 16 + 16 <= DFFN) {
                packgrp(down_w + row * DFFN + gi * 16, q);
            } else {
                float sv[16];
                #pragma unroll
                for (int j = 0; j < 16; j++) {
                    int k = gi * 16 + j;
                    sv[j] = (k < DFFN) ? down_w[row * DFFN + k] : 0.f;
                }
                __half2 o[8]; perm16(sv, o);
                *(uint4*)q = *(uint4*)o;
                *(uint4*)(q + 8) = *(uint4*)(o + 4);
            }
        }
    }
}

// ---- fp16 GEMM 128x128, 2 CTA/SM (R12 geometry) ----
// MODE 0 raw->Cf, 1 silu->Ch, 2 sigm->Cf, 5 mulAux->Cf
template <int MODE>
__global__ void __launch_bounds__(256, 2) k_gemm(
    const hf* __restrict__ A, int lda,
    const hf* __restrict__ W, int ldw, int Ntot, int KT,
    float* __restrict__ Cf, hf* __restrict__ Ch, int ldc,
    const float* __restrict__ Aux, int ldaux, int cntOv)
{
    extern __shared__ hf smh[];
    int e = blockIdx.z;
    int cnt = (cntOv >= 0) ? cntOv : g_cnt[e];
    int m0 = blockIdx.x * 128;
    if (m0 >= cnt) return;
    int n0 = blockIdx.y * 128;

    A += (size_t)e * CAP * lda;
    W += (size_t)e * Ntot * ldw;
    size_t co = (size_t)e * CAP * ldc;
    if (Cf) Cf += co;
    if (Ch) Ch += co;
    if (Aux) Aux += (size_t)e * CAP * ldaux;

    uint32_t sb = (uint32_t)__cvta_generic_to_shared(smh);
    int tid = threadIdx.x, warp = tid >> 5, lane = tid & 31;
    int wm = warp >> 1, wn = warp & 1;
    int qr = lane >> 2, qc = lane & 3;

    float acc[2][8][4];
    #pragma unroll
    for (int mt = 0; mt < 2; mt++)
        #pragma unroll
        for (int nt = 0; nt < 8; nt++)
            #pragma unroll
            for (int q = 0; q < 4; q++) acc[mt][nt][q] = 0.f;

    auto load_stage = [&](int kt, int stg) {
        int k0 = kt * KC;
        #pragma unroll
        for (int s4 = 0; s4 < 4; s4++) {
            int f = tid + s4*256, r = f >> 3, c = f & 7;
            cp16(sb + stg*STG_B + r*160 + c*16, A + (size_t)(m0 + r)*lda + k0 + c*8, true);
        }
        #pragma unroll
        for (int s4 = 0; s4 < 4; s4++) {
            int f = tid + s4*256, r = f >> 3, c = f & 7;
            bool pr = (n0 + r) < Ntot;
            const hf* gp = W + (size_t)(n0 + r)*ldw + k0 + c*8;
            cp16(sb + stg*STG_B + 20480 + r*160 + c*16, pr ? gp : W, pr);
        }
        asm volatile("cp.async.commit_group;");
    };

    load_stage(0, 0);

    for (int kt = 0; kt < KT; kt++) {
        if (kt + 1 < KT) load_stage(kt + 1, (kt + 1) & 1);
        if (kt + 1 < KT) asm volatile("cp.async.wait_group 1;");
        else             asm volatile("cp.async.wait_group 0;");
        __syncthreads();

        int stg = kt & 1;
        const hf* Asm = smh + stg * (STG_B/2);
        const hf* Bsm = Asm + 10240;

        #pragma unroll
        for (int ks = 0; ks < 4; ks++) {
            int kb = ks * 16 + qc * 4;
            uint2 a0 = *(const uint2*)(Asm + (wm*32 + qr)*RSH + kb);
            uint2 a1 = *(const uint2*)(Asm + (wm*32 + qr + 8)*RSH + kb);
            uint2 a2 = *(const uint2*)(Asm + (wm*32 + 16 + qr)*RSH + kb);
            uint2 a3 = *(const uint2*)(Asm + (wm*32 + 16 + qr + 8)*RSH + kb);
            const hf* bp = Bsm + (wn*64 + qr)*RSH + kb;
            #pragma unroll
            for (int nt = 0; nt < 8; nt++) {
                uint2 bb = *(const uint2*)(bp + nt*8*RSH);
                mma16(acc[0][nt], a0.x, a1.x, a0.y, a1.y, bb.x, bb.y);
                mma16(acc[1][nt], a2.x, a3.x, a2.y, a3.y, bb.x, bb.y);
            }
        }
        __syncthreads();
    }

    #pragma unroll
    for (int mt = 0; mt < 2; mt++) {
        #pragma unroll
        for (int nt = 0; nt < 8; nt++) {
            int n = n0 + wn*64 + nt*8 + qc*2;
            #pragma unroll
            for (int half = 0; half < 2; half++) {
                int m = m0 + wm*32 + mt*16 + qr + half*8;
                if (m >= cnt) continue;
                float v0 = acc[mt][nt][half*2], v1 = acc[mt][nt][half*2 + 1];
                if (MODE == 0) {
                    if (n < Ntot) {
                        float2 s2 = {v0, v1};
                        *(float2*)(Cf + (size_t)m * ldc + n) = s2;
                    }
                } else if (MODE == 2) {
                    if (n < Ntot) {
                        float2 s2 = {1.f/(1.f+expf(-v0)), 1.f/(1.f+expf(-v1))};
                        *(float2*)(Cf + (size_t)m * ldc + n) = s2;
                    }
                } else if (MODE == 5) {
                    if (n < Ntot) {
                        float2 s2 = {v0 * Aux[(size_t)m*ldaux + n], v1 * Aux[(size_t)m*ldaux + n + 1]};
                        *(float2*)(Cf + (size_t)m * ldc + n) = s2;
                    }
                } else {
                    if (n < Ntot) {
                        float x0 = v0/(1.f+expf(-v0)), x1 = v1/(1.f+expf(-v1));
                        size_t rowo = (size_t)m * ldc + (n & ~15);
                        *(__half2*)(Ch + rowo + posh(n & 15)) = __floats2half2_rn(x0, x1);
                    }
                }
            }
        }
    }
}

// ---- fused gate/up fp16 GEMM, 3-stage pipeline ----
__global__ void __launch_bounds__(512, 1) k_gemmF(
    const hf* __restrict__ A,
    const hf* __restrict__ Wg, const hf* __restrict__ Wu,
    hf* __restrict__ Ch)
{
    extern __shared__ hf smh[];
    int e = blockIdx.z;
    int cnt = g_cnt[e];
    int m0 = blockIdx.x * 128;
    if (m0 >= cnt) return;
    int n0 = blockIdx.y * 128;

    A  += (size_t)e * CAP * DD;
    Wg += (size_t)e * DFFN * DD;
    Wu += (size_t)e * DFFN * DD;
    Ch += (size_t)e * CAP * LDP;

    uint32_t sb = (uint32_t)__cvta_generic_to_shared(smh);
    int tid = threadIdx.x, warp = tid >> 5, lane = tid & 31;
    int wm = warp >> 3, wn = warp & 7;
    int qr = lane >> 2, qc = lane & 3;

    float accG[4][2][4], accU[4][2][4];
    #pragma unroll
    for (int mt = 0; mt < 4; mt++)
        #pragma unroll
        for (int nt = 0; nt < 2; nt++)
            #pragma unroll
            for (int q = 0; q < 4; q++) { accG[mt][nt][q] = 0.f; accU[mt][nt][q] = 0.f; }

    auto load_stage = [&](int kt, int stg) {
        int k0 = kt * KC;
        #pragma unroll
        for (int i = 0; i < 6; i++) {
            int f = tid + i*512, r = f >> 3, c = f & 7;
            const hf* gp; bool pr = true;
            if (r < 128) {
                gp = A + (size_t)(m0 + r)*DD + k0 + c*8;
            } else if (r < 256) {
                int nr = n0 + r - 128; pr = nr < DFFN;
                gp = pr ? (Wg + (size_t)nr*DD + k0 + c*8) : A;
            } else {
                int nr = n0 + r - 256; pr = nr < DFFN;
                gp = pr ? (Wu + (size_t)nr*DD + k0 + c*8) : A;
            }
            cp16(sb + stg*STG_BF + r*160 + c*16, gp, pr);
        }
        asm volatile("cp.async.commit_group;");
    };

    const int KT = DD / KC;
    load_stage(0, 0);
    load_stage(1, 1);

    for (int kt = 0; kt < KT; kt++) {
        if (kt + 1 < KT) asm volatile("cp.async.wait_group 1;");
        else             asm volatile("cp.async.wait_group 0;");
        __syncthreads();
        if (kt + 2 < KT) load_stage(kt + 2, (kt + 2) % 3);

        int stg = kt % 3;
        const hf* Asm = smh + stg * (STG_BF/2);
        const hf* Gsm = Asm + 10240;
        const hf* Usm = Asm + 20480;

        #pragma unroll
        for (int ks = 0; ks < 4; ks++) {
            int kb = ks * 16 + qc * 4;
            uint2 al[4], ah[4];
            #pragma unroll
            for (int mt = 0; mt < 4; mt++) {
                al[mt] = *(const uint2*)(Asm + (wm*64 + mt*16 + qr)*RSH + kb);
                ah[mt] = *(const uint2*)(Asm + (wm*64 + mt*16 + qr + 8)*RSH + kb);
            }
            #pragma unroll
            for (int nt = 0; nt < 2; nt++) {
                int br = (wn*16 + nt*8 + qr)*RSH + kb;
                uint2 bg = *(const uint2*)(Gsm + br);
                uint2 bu = *(const uint2*)(Usm + br);
                #pragma unroll
                for (int mt = 0; mt < 4; mt++) {
                    mma16(accG[mt][nt], al[mt].x, ah[mt].x, al[mt].y, ah[mt].y, bg.x, bg.y);
                    mma16(accU[mt][nt], al[mt].x, ah[mt].x, al[mt].y, ah[mt].y, bu.x, bu.y);
                }
            }
        }
        __syncthreads();
    }

    #pragma unroll
    for (int mt = 0; mt < 4; mt++) {
        #pragma unroll
        for (int nt = 0; nt < 2; nt++) {
            int n = n0 + wn*16 + nt*8 + qc*2;
            #pragma unroll
            for (int half = 0; half < 2; half++) {
                int m = m0 + wm*64 + mt*16 + qr + half*8;
                if (m >= cnt) continue;
                size_t rowo = (size_t)m * LDP + (n & ~15);
                int p0 = posh(n & 15);
                if (n < DFFN) {
                    float gv0 = accG[mt][nt][half*2], gv1 = accG[mt][nt][half*2 + 1];
                    float uv0 = accU[mt][nt][half*2], uv1 = accU[mt][nt][half*2 + 1];
                    float x0 = (gv0/(1.f+expf(-gv0))) * uv0;
                    float x1 = (gv1/(1.f+expf(-gv1))) * uv1;
                    *(__half2*)(Ch + rowo + p0) = __floats2half2_rn(x0, x1);
                } else if (n < LDP) {
                    *(__half2*)(Ch + rowo + p0) = __floats2half2_rn(0.f, 0.f);
                }
            }
        }
    }
}

// ---- per-token: gates, sinkhorn, h, hn ----
__global__ void __launch_bounds__(128) k_hn(const float* __restrict__ stream,
                                            const float* __restrict__ b_pre,
                                            const float* __restrict__ b_post,
                                            const float* __restrict__ b_res,
                                            const float* __restrict__ alpha_pre,
                                            const float* __restrict__ alpha_post,
                                            const float* __restrict__ alpha_res,
                                            const float* __restrict__ sw_norm_w)
{
    int token = blockIdx.x, b = token / TT, t = token % TT, tid = threadIdx.x;
    __shared__ float hpre[NS], red2[4];
    int lane = tid & 31, warp = tid >> 5;

    const float* sp0 = stream + ((size_t)b*NS*TT + t) * DD;
    float st[4][8];
    #pragma unroll
    for (int i = 0; i < 4; i++)
        #pragma unroll
        for (int u = 0; u < 8; u++)
            st[i][u] = sp0[(size_t)i*TT*DD + tid + u*128];

    for (int e = 0; e < EE; e++) {
        int row = g_row[token*EE + e];
        if (row < 0) continue;
        __syncthreads();
        if (tid == 0) {
            const float* d = g_dots + (size_t)token*384 + e*24;
            size_t slot = (size_t)e*CAP + row;
            float ap = alpha_pre[e], ao = alpha_post[e], ar = alpha_res[e];
            #pragma unroll
            for (int i = 0; i < NS; i++)
                hpre[i] = 1.f / (1.f + expf(-(ap*d[i] + b_pre[e*NS+i])));
            #pragma unroll
            for (int i = 0; i < NS; i++)
                g_Hpost[slot*NS+i] = 2.f / (1.f + expf(-(ao*d[4+i] + b_post[e*NS+i])));
            float M[16];
            #pragma unroll
            for (int k = 0; k < 16; k++) M[k] = expf(ar*d[8+k] + b_res[e*16+k]);
            for (int it = 0; it < 6; it++) {
                #pragma unroll
                for (int i = 0; i < 4; i++) {
                    float ir = 1.f / (M[i*4]+M[i*4+1]+M[i*4+2]+M[i*4+3]);
                    M[i*4]*=ir; M[i*4+1]*=ir; M[i*4+2]*=ir; M[i*4+3]*=ir;
                }
                #pragma unroll
                for (int j = 0; j < 4; j++) {
                    float ic = 1.f / (M[j]+M[4+j]+M[8+j]+M[12+j]);
                    M[j]*=ic; M[4+j]*=ic; M[8+j]*=ic; M[12+j]*=ic;
                }
            }
            #pragma unroll
            for (int k = 0; k < 16; k++) g_Hres[slot*16+k] = M[k];
        }
        __syncthreads();

        float h0 = hpre[0], h1 = hpre[1], h2 = hpre[2], h3 = hpre[3];
        float hreg[8], hq = 0.f;
        #pragma unroll
        for (int u = 0; u < 8; u++) {
            float h = h0*st[0][u] + h1*st[1][u] + h2*st[2][u] + h3*st[3][u];
            hreg[u] = h; hq += h*h;
        }
        #pragma unroll
        for (int o = 16; o > 0; o >>= 1) hq += __shfl_down_sync(0xffffffffu, hq, o);
        if (lane == 0) red2[warp] = hq;
        __syncthreads();
        float sh = rsqrtf((red2[0]+red2[1]+red2[2]+red2[3]) / (float)DD + EPS_F);
        const float* snw = sw_norm_w + (size_t)e*DD;
        hf* hn = g_HN + ((size_t)e*CAP + row) * DD;
        #pragma unroll
        for (int u = 0; u < 8; u++) {
            int dd = tid + u*128;
            float v = hreg[u] * sh * snw[dd];
            hn[(dd & ~15) + posh(dd & 15)] = __float2half_rn(v);
        }
    }
}

// ---- combine res + post ----
__global__ void __launch_bounds__(128) k_out(const float* __restrict__ stream,
                                             float* __restrict__ outp)
{
    int token = blockIdx.x, b = token / TT, t = token % TT, tid = threadIdx.x;
    const float* sp0 = stream + ((size_t)b*NS*TT + t) * DD;
    float st[4][8], acc[4][8];
    #pragma unroll
    for (int i = 0; i < 4; i++)
        #pragma unroll
        for (int j = 0; j < 8; j++) {
            st[i][j] = sp0[(size_t)i*TT*DD + tid + j*128];
            acc[i][j] = 0.f;
        }
    for (int e = 0; e < EE; e++) {
        int row = g_row[token*EE + e];
        if (row < 0) continue;
        float g = g_gatev[token*EE + e];
        size_t slot = (size_t)e*CAP + row;
        float Hr[16], Hp[4];
        #pragma unroll
        for (int k = 0; k < 16; k++) Hr[k] = g_Hres[slot*16+k];
        #pragma unroll
        for (int i = 0; i < 4; i++) Hp[i] = g_Hpost[slot*4+i];
        const float* o = g_OUT + slot*DD;
        #pragma unroll
        for (int j = 0; j < 8; j++) {
            float ov = o[tid + j*128];
            #pragma unroll
            for (int i = 0; i < 4; i++) {
                float r = Hr[i*4]*st[0][j] + Hr[i*4+1]*st[1][j]
                        + Hr[i*4+2]*st[2][j] + Hr[i*4+3]*st[3][j];
                acc[i][j] += g * (r + Hp[i]*ov);
            }
        }
    }
    #pragma unroll
    for (int i = 0; i < 4; i++)
        #pragma unroll
        for (int j = 0; j < 8; j++)
            outp[((size_t)(b*NS+i)*TT + t)*DD + tid + j*128] = acc[i][j];
}

#define GSA(p, s) cudaGetSymbolAddress((void**)&p, s)

extern "C" void kernel_launch(void* const* d_in, const int* in_sizes, int n_in,
                              void* d_out, int out_size)
{
    (void)in_sizes; (void)n_in; (void)out_size;
    const float* stream   = (const float*)d_in[0];
    const float* router_w = (const float*)d_in[1];
    const float* mhc      = (const float*)d_in[2];
    const float* phi_pre  = (const float*)d_in[3];
    const float* phi_post = (const float*)d_in[4];
    const float* phi_res  = (const float*)d_in[5];
    const float* b_pre    = (const float*)d_in[6];
    const float* b_post   = (const float*)d_in[7];
    const float* b_res    = (const float*)d_in[8];
    const float* a_pre    = (const float*)d_in[9];
    const float* a_post   = (const float*)d_in[10];
    const float* a_res    = (const float*)d_in[11];
    const float* sw_nw    = (const float*)d_in[12];
    const float* wd_w     = (const float*)d_in[13];
    const float* wu_w     = (const float*)d_in[14];
    const float* gate_w   = (const float*)d_in[15];
    const float* up_w     = (const float*)d_in[16];
    const float* down_w   = (const float*)d_in[17];

    float* outp = (float*)d_out;
    float* out_gate = outp + (size_t)BB*NS*TT*DD;

    cudaFuncSetAttribute(k_gemm<0>, cudaFuncAttributeMaxDynamicSharedMemorySize, SMEM_DYN);
    cudaFuncSetAttribute(k_gemm<1>, cudaFuncAttributeMaxDynamicSharedMemorySize, SMEM_DYN);
    cudaFuncSetAttribute(k_gemm<2>, cudaFuncAttributeMaxDynamicSharedMemorySize, SMEM_DYN);
    cudaFuncSetAttribute(k_gemm<5>, cudaFuncAttributeMaxDynamicSharedMemorySize, SMEM_DYN);
    cudaFuncSetAttribute(k_gemmF, cudaFuncAttributeMaxDynamicSharedMemorySize, SMEM_F);

    hf *base, *HN, *T1, *P2, *phiW, *gt, *up, *dn, *wd, *wu;
    float *GS, *OUT, *dots;
    GSA(base, g_base); GSA(HN, g_HN); GSA(T1, g_T1); GSA(P2, g_P2);
    GSA(phiW, g_phiW); GSA(wd, g_wd); GSA(wu, g_wu); GSA(gt, g_gt);
    GSA(up, g_up); GSA(dn, g_dn);
    GSA(GS, g_GS); GSA(OUT, g_OUT); GSA(dots, g_dots);

    k_zero<<<1, 32>>>();
    k_gate<<<BT, 256>>>(stream, router_w, out_gate);
    k_pack<<<(EE*24*NDIM/16)/256, 256>>>(mhc, phi_pre, phi_post, phi_res);
    k_packall<<<4096, 256>>>(wd_w, wu_w, gate_w, up_w, down_w);

    // dots = base @ phiW^T  (N=384, K=4096)
    k_gemm<0><<<dim3(32,3,1), 256, SMEM_DYN>>>(base, NDIM, phiW, NDIM, 384, NDIM/KC,
                                               dots, (hf*)0, 384, (const float*)0, 0, BT);

    k_hn<<<BT, 128>>>(stream, b_pre, b_post, b_res, a_pre, a_post, a_res, sw_nw);

    dim3 gD(32, 8, EE);

    // T1 = silu(HN @ wd^T) -> interleaved half
    k_gemm<1><<<gD, 256, SMEM_DYN>>>(HN, DD, wd, DD, DD, DD/KC,
                                     (float*)0, T1, DD, (const float*)0, 0, -1);
    // GS = sigmoid(T1 @ wu^T) -> f32
    k_gemm<2><<<gD, 256, SMEM_DYN>>>(T1, DD, wu, DD, DD, DD/KC,
                                     GS, (hf*)0, DD, (const float*)0, 0, -1);
    // P2 = silu(HN @ gt^T) * (HN @ up^T) -> interleaved half
    k_gemmF<<<dim3(32,13,EE), 512, SMEM_F>>>(HN, gt, up, P2);
    // OUT = (P2 @ dn^T) * GS -> f32
    k_gemm<5><<<gD, 256, SMEM_DYN>>>(P2, LDP, dn, LDP, DD, LDP/KC,
                                     OUT, (hf*)0, DD, GS, DD, -1);

    k_out<<<BT, 128>>>(stream, outp);
}

// round 15
// speedup vs baseline: 1.0541x; 1.0082x over previous
#include <cuda_runtime.h>
#include <cuda_fp16.h>
#include <math.h>
#include <stdint.h>

#define BB 2
#define NS 4
#define TT 2048
#define DD 1024
#define EE 16
#define NDIM 4096
#define DFFN 1656
#define LDP 1664
#define BT (BB*TT)
#define CAP BT
#define EPS_F 1.1920929e-7f
#define RSH 80
#define KC 64
#define STG_B 40960
#define SMEM_DYN (2*STG_B)
#define STG_BF 61440
#define SMEM_F (2*STG_BF)

typedef __half hf;

// ---- device scratch ----
__device__ __align__(16) hf g_base[(size_t)BT*NDIM];
__device__ __align__(16) hf g_HN [(size_t)EE*CAP*DD];
__device__ __align__(16) hf g_T1 [(size_t)EE*CAP*DD];
__device__ __align__(16) hf g_P2 [(size_t)EE*CAP*LDP];
__device__ __align__(16) hf g_phiW[(size_t)EE*24*NDIM];
__device__ __align__(16) hf g_wd[(size_t)EE*DD*DD];
__device__ __align__(16) hf g_wu[(size_t)EE*DD*DD];
__device__ __align__(16) hf g_gt[(size_t)EE*DFFN*DD];
__device__ __align__(16) hf g_up[(size_t)EE*DFFN*DD];
__device__ __align__(16) hf g_dn[(size_t)EE*DD*LDP];
__device__ __align__(16) float g_GS [(size_t)EE*CAP*DD];
__device__ __align__(16) float g_OUT[(size_t)EE*CAP*DD];
__device__ __align__(16) float g_dots[(size_t)BT*384];
__device__ int   g_row[BT*EE];
__device__ float g_gatev[BT*EE];
__device__ int   g_cnt[EE];
__device__ int   g_tok[EE*CAP];
__device__ float g_Hpost[(size_t)EE*CAP*NS];
__device__ float g_Hres[(size_t)EE*CAP*16];

#define N1G 1048576L            // EE*DD*DD/16   (wd, wu)
#define N2G 1695744L            // EE*DFFN*DD/16 (gt, up)
#define N3G 1703936L            // EE*DD*LDP/16  (dn)
#define N4G 98304L              // EE*24*NDIM/16 (phi)
#define NTOTG (2*N1G + 2*N2G + N3G + N4G)

// ---- helpers ----
__device__ __forceinline__ int posh(int n) {
    return ((n >> 1) & 3) * 4 + ((n >> 3) & 1) * 2 + (n & 1);
}
__device__ __forceinline__ void perm16(const float* s, __half2* o) {
    const int pr[8] = {0, 8, 2, 10, 4, 12, 6, 14};
    #pragma unroll
    for (int j = 0; j < 8; j++)
        o[j] = __floats2half2_rn(s[pr[j]], s[pr[j] + 1]);
}
__device__ __forceinline__ void mma16(float* c, uint32_t a0, uint32_t a1, uint32_t a2,
                                      uint32_t a3, uint32_t b0, uint32_t b1) {
    asm volatile(
        "mma.sync.aligned.m16n8k16.row.col.f32.f16.f16.f32 "
        "{%0,%1,%2,%3}, {%4,%5,%6,%7}, {%8,%9}, {%0,%1,%2,%3};"
        : "+f"(c[0]), "+f"(c[1]), "+f"(c[2]), "+f"(c[3])
        : "r"(a0), "r"(a1), "r"(a2), "r"(a3), "r"(b0), "r"(b1));
}
__device__ __forceinline__ void cp16(uint32_t s, const void* g, bool pr) {
    int b = pr ? 16 : 0;
    asm volatile("cp.async.cg.shared.global [%0], [%1], 16, %2;" :: "r"(s), "l"(g), "r"(b));
}

__global__ void k_zero() { if (threadIdx.x < EE) g_cnt[threadIdx.x] = 0; }

// ---- router gate + token rms + base emit (fused) ----
__global__ void __launch_bounds__(256) k_gate(const float* __restrict__ stream,
                                              const float* __restrict__ router_w,
                                              float* __restrict__ out_gate)
{
    int token = blockIdx.x, b = token / TT, t = token % TT, tid = threadIdx.x;
    __shared__ float route[DD], red[256], logit[EE];
    const float* sp0 = stream + ((size_t)b * NS * TT + t) * DD;
    float v[4][4];
    float ss = 0.f;
    #pragma unroll
    for (int it = 0; it < 4; it++) {
        int dd = tid + it * 256;
        float v0 = sp0[dd], v1 = sp0[(size_t)TT*DD + dd];
        float v2 = sp0[2*(size_t)TT*DD + dd], v3 = sp0[3*(size_t)TT*DD + dd];
        v[it][0] = v0; v[it][1] = v1; v[it][2] = v2; v[it][3] = v3;
        ss += v0*v0 + v1*v1 + v2*v2 + v3*v3;
        route[dd] = 0.25f * (v0 + v1 + v2 + v3);
    }
    red[tid] = ss; __syncthreads();
    for (int s = 128; s > 0; s >>= 1) { if (tid < s) red[tid] += red[tid+s]; __syncthreads(); }
    float srms = rsqrtf(red[0] / (float)NDIM + EPS_F);

    hf* dst = g_base + (size_t)token * NDIM;
    #pragma unroll
    for (int it = 0; it < 4; it++) {
        int dd = tid + it * 256;
        #pragma unroll
        for (int i = 0; i < 4; i++) {
            int j = i * 1024 + dd;
            dst[(j & ~15) | posh(j & 15)] = __float2half_rn(v[it][i] * srms);
        }
    }

    int warp = tid >> 5, lane = tid & 31;
    for (int e = warp; e < EE; e += 8) {
        const float* rw = router_w + (size_t)e * DD;
        float acc = 0.f;
        for (int dd = lane; dd < DD; dd += 32) acc += route[dd] * rw[dd];
        #pragma unroll
        for (int o = 16; o > 0; o >>= 1) acc += __shfl_down_sync(0xffffffffu, acc, o);
        if (lane == 0) logit[e] = acc;
    }
    __syncthreads();
    if (tid == 0) {
        float p[EE], mx = -1e30f;
        #pragma unroll
        for (int e = 0; e < EE; e++) mx = fmaxf(mx, logit[e]);
        float sum = 0.f;
        #pragma unroll
        for (int e = 0; e < EE; e++) { p[e] = expf(logit[e] - mx); sum += p[e]; }
        float inv = 1.f / sum;
        #pragma unroll
        for (int e = 0; e < EE; e++) p[e] *= inv;
        int ord[EE];
        #pragma unroll
        for (int e = 0; e < EE; e++) ord[e] = e;
        for (int i = 1; i < EE; i++) {
            int oi = ord[i]; float pi = p[oi]; int j = i - 1;
            while (j >= 0 && p[ord[j]] < pi) { ord[j+1] = ord[j]; j--; }
            ord[j+1] = oi;
        }
        float cum = 0.f, gate[EE];
        #pragma unroll
        for (int e = 0; e < EE; e++) gate[e] = 0.f;
        for (int r = 0; r < EE; r++) {
            int e = ord[r];
            if ((r == 0) || (cum < 0.8f && r < 4)) gate[e] = p[e];
            cum += p[e];
        }
        for (int e = 0; e < EE; e++) {
            float g = gate[e];
            out_gate[(size_t)token*EE + e] = g;
            g_gatev[token*EE + e] = g;
            int row = -1;
            if (g > 0.f) { row = atomicAdd(&g_cnt[e], 1); g_tok[e*CAP + row] = token; }
            g_row[token*EE + e] = row;
        }
    }
}

// ---- merged weight pack: wd/wu/gt/up/dn + phi, one grid-stride kernel ----
__device__ __forceinline__ void packgrp(const float* p, hf* q) {
    float sv[16];
    #pragma unroll
    for (int c = 0; c < 4; c++) {
        float4 v = *(const float4*)(p + c*4);
        sv[c*4+0] = v.x; sv[c*4+1] = v.y; sv[c*4+2] = v.z; sv[c*4+3] = v.w;
    }
    __half2 o[8]; perm16(sv, o);
    *(uint4*)q = *(uint4*)o;
    *(uint4*)(q + 8) = *(uint4*)(o + 4);
}
__global__ void __launch_bounds__(256) k_packall(const float* __restrict__ wd_w,
                                                 const float* __restrict__ wu_w,
                                                 const float* __restrict__ gate_w,
                                                 const float* __restrict__ up_w,
                                                 const float* __restrict__ down_w,
                                                 const float* __restrict__ mhc,
                                                 const float* __restrict__ pw,
                                                 const float* __restrict__ ow,
                                                 const float* __restrict__ rw)
{
    long g0 = (long)blockIdx.x * 256 + threadIdx.x;
    long stride = (long)gridDim.x * 256;
    for (long g = g0; g < NTOTG; g += stride) {
        if (g < 2*N1G) {
            long l = (g < N1G) ? g : g - N1G;
            const float* src = (g < N1G) ? wd_w : wu_w;
            hf* dst = (g < N1G) ? g_wd : g_wu;
            long row = l >> 6; int gi = (int)(l & 63);
            packgrp(src + row * DD + gi * 16, dst + l * 16);
        } else if (g < 2*N1G + 2*N2G) {
            long l = g - 2*N1G;
            const float* src = (l < N2G) ? gate_w : up_w;
            hf* dst = (l < N2G) ? g_gt : g_up;
            if (l >= N2G) l -= N2G;
            long row = l >> 6; int gi = (int)(l & 63);
            packgrp(src + row * DD + gi * 16, dst + l * 16);
        } else if (g < 2*N1G + 2*N2G + N3G) {
            long l = g - 2*N1G - 2*N2G;
            long row = l / 104; int gi = (int)(l - row * 104);
            hf* q = g_dn + l * 16;
            if (gi * 16 + 16 <= DFFN) {
                packgrp(down_w + row * DFFN + gi * 16, q);
            } else {
                float sv[16];
                #pragma unroll
                for (int j = 0; j < 16; j++) {
                    int k = gi * 16 + j;
                    sv[j] = (k < DFFN) ? down_w[row * DFFN + k] : 0.f;
                }
                __half2 o[8]; perm16(sv, o);
                *(uint4*)q = *(uint4*)o;
                *(uint4*)(q + 8) = *(uint4*)(o + 4);
            }
        } else {                              // phi segment: fold mhc norm
            long l = g - 2*N1G - 2*N2G - N3G; // 0 .. N4G
            int e = (int)(l / 6144);
            int rem = (int)(l - (long)e * 6144);
            int r = rem >> 8;
            int j0 = (rem & 255) * 16;
            const float* wsrc;
            if (r < 4)      wsrc = pw + ((size_t)e*4 + r)*NDIM + j0;
            else if (r < 8) wsrc = ow + ((size_t)e*4 + (r-4))*NDIM + j0;
            else            wsrc = rw + ((size_t)e*16 + (r-8))*NDIM + j0;
            const float* nsrc = mhc + (size_t)e*NDIM + j0;
            float sv[16];
            #pragma unroll
            for (int q2 = 0; q2 < 4; q2++) {
                float4 w = *(const float4*)(wsrc + q2*4);
                float4 n = *(const float4*)(nsrc + q2*4);
                sv[q2*4+0] = w.x*n.x; sv[q2*4+1] = w.y*n.y;
                sv[q2*4+2] = w.z*n.z; sv[q2*4+3] = w.w*n.w;
            }
            __half2 o[8]; perm16(sv, o);
            hf* q = g_phiW + l * 16;
            *(uint4*)q = *(uint4*)o;
            *(uint4*)(q + 8) = *(uint4*)(o + 4);
        }
    }
}

// ---- fp16 GEMM 128x128, 2 CTA/SM ----
// MODE 0 raw->Cf, 1 silu->Ch, 2 sigm->Cf, 5 mulAux->Cf
template <int MODE>
__global__ void __launch_bounds__(256, 2) k_gemm(
    const hf* __restrict__ A, int lda,
    const hf* __restrict__ W, int ldw, int Ntot, int KT,
    float* __restrict__ Cf, hf* __restrict__ Ch, int ldc,
    const float* __restrict__ Aux, int ldaux, int cntOv)
{
    extern __shared__ hf smh[];
    int e = blockIdx.z;
    int cnt = (cntOv >= 0) ? cntOv : g_cnt[e];
    int m0 = blockIdx.x * 128;
    if (m0 >= cnt) return;
    int n0 = blockIdx.y * 128;

    A += (size_t)e * CAP * lda;
    W += (size_t)e * Ntot * ldw;
    size_t co = (size_t)e * CAP * ldc;
    if (Cf) Cf += co;
    if (Ch) Ch += co;
    if (Aux) Aux += (size_t)e * CAP * ldaux;

    uint32_t sb = (uint32_t)__cvta_generic_to_shared(smh);
    int tid = threadIdx.x, warp = tid >> 5, lane = tid & 31;
    int wm = warp >> 1, wn = warp & 1;
    int qr = lane >> 2, qc = lane & 3;

    float acc[2][8][4];
    #pragma unroll
    for (int mt = 0; mt < 2; mt++)
        #pragma unroll
        for (int nt = 0; nt < 8; nt++)
            #pragma unroll
            for (int q = 0; q < 4; q++) acc[mt][nt][q] = 0.f;

    auto load_stage = [&](int kt, int stg) {
        int k0 = kt * KC;
        #pragma unroll
        for (int s4 = 0; s4 < 4; s4++) {
            int f = tid + s4*256, r = f >> 3, c = f & 7;
            cp16(sb + stg*STG_B + r*160 + c*16, A + (size_t)(m0 + r)*lda + k0 + c*8, true);
        }
        #pragma unroll
        for (int s4 = 0; s4 < 4; s4++) {
            int f = tid + s4*256, r = f >> 3, c = f & 7;
            bool pr = (n0 + r) < Ntot;
            const hf* gp = W + (size_t)(n0 + r)*ldw + k0 + c*8;
            cp16(sb + stg*STG_B + 20480 + r*160 + c*16, pr ? gp : W, pr);
        }
        asm volatile("cp.async.commit_group;");
    };

    load_stage(0, 0);

    for (int kt = 0; kt < KT; kt++) {
        if (kt + 1 < KT) load_stage(kt + 1, (kt + 1) & 1);
        if (kt + 1 < KT) asm volatile("cp.async.wait_group 1;");
        else             asm volatile("cp.async.wait_group 0;");
        __syncthreads();

        int stg = kt & 1;
        const hf* Asm = smh + stg * (STG_B/2);
        const hf* Bsm = Asm + 10240;

        #pragma unroll
        for (int ks = 0; ks < 4; ks++) {
            int kb = ks * 16 + qc * 4;
            uint2 a0 = *(const uint2*)(Asm + (wm*32 + qr)*RSH + kb);
            uint2 a1 = *(const uint2*)(Asm + (wm*32 + qr + 8)*RSH + kb);
            uint2 a2 = *(const uint2*)(Asm + (wm*32 + 16 + qr)*RSH + kb);
            uint2 a3 = *(const uint2*)(Asm + (wm*32 + 16 + qr + 8)*RSH + kb);
            const hf* bp = Bsm + (wn*64 + qr)*RSH + kb;
            #pragma unroll
            for (int nt = 0; nt < 8; nt++) {
                uint2 bb = *(const uint2*)(bp + nt*8*RSH);
                mma16(acc[0][nt], a0.x, a1.x, a0.y, a1.y, bb.x, bb.y);
                mma16(acc[1][nt], a2.x, a3.x, a2.y, a3.y, bb.x, bb.y);
            }
        }
        __syncthreads();
    }

    #pragma unroll
    for (int mt = 0; mt < 2; mt++) {
        #pragma unroll
        for (int nt = 0; nt < 8; nt++) {
            int n = n0 + wn*64 + nt*8 + qc*2;
            #pragma unroll
            for (int half = 0; half < 2; half++) {
                int m = m0 + wm*32 + mt*16 + qr + half*8;
                if (m >= cnt) continue;
                float v0 = acc[mt][nt][half*2], v1 = acc[mt][nt][half*2 + 1];
                if (MODE == 0) {
                    if (n < Ntot) {
                        float2 s2 = {v0, v1};
                        *(float2*)(Cf + (size_t)m * ldc + n) = s2;
                    }
                } else if (MODE == 2) {
                    if (n < Ntot) {
                        float2 s2 = {1.f/(1.f+expf(-v0)), 1.f/(1.f+expf(-v1))};
                        *(float2*)(Cf + (size_t)m * ldc + n) = s2;
                    }
                } else if (MODE == 5) {
                    if (n < Ntot) {
                        float2 s2 = {v0 * Aux[(size_t)m*ldaux + n], v1 * Aux[(size_t)m*ldaux + n + 1]};
                        *(float2*)(Cf + (size_t)m * ldc + n) = s2;
                    }
                } else {
                    if (n < Ntot) {
                        float x0 = v0/(1.f+expf(-v0)), x1 = v1/(1.f+expf(-v1));
                        size_t rowo = (size_t)m * ldc + (n & ~15);
                        *(__half2*)(Ch + rowo + posh(n & 15)) = __floats2half2_rn(x0, x1);
                    }
                }
            }
        }
    }
}

// ---- fused gate/up fp16 GEMM (2-stage, R12) ----
__global__ void __launch_bounds__(512, 1) k_gemmF(
    const hf* __restrict__ A,
    const hf* __restrict__ Wg, const hf* __restrict__ Wu,
    hf* __restrict__ Ch)
{
    extern __shared__ hf smh[];
    int e = blockIdx.z;
    int cnt = g_cnt[e];
    int m0 = blockIdx.x * 128;
    if (m0 >= cnt) return;
    int n0 = blockIdx.y * 128;

    A  += (size_t)e * CAP * DD;
    Wg += (size_t)e * DFFN * DD;
    Wu += (size_t)e * DFFN * DD;
    Ch += (size_t)e * CAP * LDP;

    uint32_t sb = (uint32_t)__cvta_generic_to_shared(smh);
    int tid = threadIdx.x, warp = tid >> 5, lane = tid & 31;
    int wm = warp >> 3, wn = warp & 7;
    int qr = lane >> 2, qc = lane & 3;

    float accG[4][2][4], accU[4][2][4];
    #pragma unroll
    for (int mt = 0; mt < 4; mt++)
        #pragma unroll
        for (int nt = 0; nt < 2; nt++)
            #pragma unroll
            for (int q = 0; q < 4; q++) { accG[mt][nt][q] = 0.f; accU[mt][nt][q] = 0.f; }

    auto load_stage = [&](int kt, int stg) {
        int k0 = kt * KC;
        #pragma unroll
        for (int i = 0; i < 6; i++) {
            int f = tid + i*512, r = f >> 3, c = f & 7;
            const hf* gp; bool pr = true;
            if (r < 128) {
                gp = A + (size_t)(m0 + r)*DD + k0 + c*8;
            } else if (r < 256) {
                int nr = n0 + r - 128; pr = nr < DFFN;
                gp = pr ? (Wg + (size_t)nr*DD + k0 + c*8) : A;
            } else {
                int nr = n0 + r - 256; pr = nr < DFFN;
                gp = pr ? (Wu + (size_t)nr*DD + k0 + c*8) : A;
            }
            cp16(sb + stg*STG_BF + r*160 + c*16, gp, pr);
        }
        asm volatile("cp.async.commit_group;");
    };

    const int KT = DD / KC;
    load_stage(0, 0);

    for (int kt = 0; kt < KT; kt++) {
        if (kt + 1 < KT) load_stage(kt + 1, (kt + 1) & 1);
        if (kt + 1 < KT) asm volatile("cp.async.wait_group 1;");
        else             asm volatile("cp.async.wait_group 0;");
        __syncthreads();

        int stg = kt & 1;
        const hf* Asm = smh + stg * (STG_BF/2);
        const hf* Gsm = Asm + 10240;
        const hf* Usm = Asm + 20480;

        #pragma unroll
        for (int ks = 0; ks < 4; ks++) {
            int kb = ks * 16 + qc * 4;
            uint2 al[4], ah[4];
            #pragma unroll
            for (int mt = 0; mt < 4; mt++) {
                al[mt] = *(const uint2*)(Asm + (wm*64 + mt*16 + qr)*RSH + kb);
                ah[mt] = *(const uint2*)(Asm + (wm*64 + mt*16 + qr + 8)*RSH + kb);
            }
            #pragma unroll
            for (int nt = 0; nt < 2; nt++) {
                int br = (wn*16 + nt*8 + qr)*RSH + kb;
                uint2 bg = *(const uint2*)(Gsm + br);
                uint2 bu = *(const uint2*)(Usm + br);
                #pragma unroll
                for (int mt = 0; mt < 4; mt++) {
                    mma16(accG[mt][nt], al[mt].x, ah[mt].x, al[mt].y, ah[mt].y, bg.x, bg.y);
                    mma16(accU[mt][nt], al[mt].x, ah[mt].x, al[mt].y, ah[mt].y, bu.x, bu.y);
                }
            }
        }
        __syncthreads();
    }

    #pragma unroll
    for (int mt = 0; mt < 4; mt++) {
        #pragma unroll
        for (int nt = 0; nt < 2; nt++) {
            int n = n0 + wn*16 + nt*8 + qc*2;
            #pragma unroll
            for (int half = 0; half < 2; half++) {
                int m = m0 + wm*64 + mt*16 + qr + half*8;
                if (m >= cnt) continue;
                size_t rowo = (size_t)m * LDP + (n & ~15);
                int p0 = posh(n & 15);
                if (n < DFFN) {
                    float gv0 = accG[mt][nt][half*2], gv1 = accG[mt][nt][half*2 + 1];
                    float uv0 = accU[mt][nt][half*2], uv1 = accU[mt][nt][half*2 + 1];
                    float x0 = (gv0/(1.f+expf(-gv0))) * uv0;
                    float x1 = (gv1/(1.f+expf(-gv1))) * uv1;
                    *(__half2*)(Ch + rowo + p0) = __floats2half2_rn(x0, x1);
                } else if (n < LDP) {
                    *(__half2*)(Ch + rowo + p0) = __floats2half2_rn(0.f, 0.f);
                }
            }
        }
    }
}

// ---- per-token: gates, sinkhorn, h, hn ----
__global__ void __launch_bounds__(128) k_hn(const float* __restrict__ stream,
                                            const float* __restrict__ b_pre,
                                            const float* __restrict__ b_post,
                                            const float* __restrict__ b_res,
                                            const float* __restrict__ alpha_pre,
                                            const float* __restrict__ alpha_post,
                                            const float* __restrict__ alpha_res,
                                            const float* __restrict__ sw_norm_w)
{
    int token = blockIdx.x, b = token / TT, t = token % TT, tid = threadIdx.x;
    __shared__ float hpre[NS], red2[4];
    int lane = tid & 31, warp = tid >> 5;

    const float* sp0 = stream + ((size_t)b*NS*TT + t) * DD;
    float st[4][8];
    #pragma unroll
    for (int i = 0; i < 4; i++)
        #pragma unroll
        for (int u = 0; u < 8; u++)
            st[i][u] = sp0[(size_t)i*TT*DD + tid + u*128];

    for (int e = 0; e < EE; e++) {
        int row = g_row[token*EE + e];
        if (row < 0) continue;
        __syncthreads();
        if (tid == 0) {
            const float* d = g_dots + (size_t)token*384 + e*24;
            size_t slot = (size_t)e*CAP + row;
            float ap = alpha_pre[e], ao = alpha_post[e], ar = alpha_res[e];
            #pragma unroll
            for (int i = 0; i < NS; i++)
                hpre[i] = 1.f / (1.f + expf(-(ap*d[i] + b_pre[e*NS+i])));
            #pragma unroll
            for (int i = 0; i < NS; i++)
                g_Hpost[slot*NS+i] = 2.f / (1.f + expf(-(ao*d[4+i] + b_post[e*NS+i])));
            float M[16];
            #pragma unroll
            for (int k = 0; k < 16; k++) M[k] = expf(ar*d[8+k] + b_res[e*16+k]);
            for (int it = 0; it < 6; it++) {
                #pragma unroll
                for (int i = 0; i < 4; i++) {
                    float ir = 1.f / (M[i*4]+M[i*4+1]+M[i*4+2]+M[i*4+3]);
                    M[i*4]*=ir; M[i*4+1]*=ir; M[i*4+2]*=ir; M[i*4+3]*=ir;
                }
                #pragma unroll
                for (int j = 0; j < 4; j++) {
                    float ic = 1.f / (M[j]+M[4+j]+M[8+j]+M[12+j]);
                    M[j]*=ic; M[4+j]*=ic; M[8+j]*=ic; M[12+j]*=ic;
                }
            }
            #pragma unroll
            for (int k = 0; k < 16; k++) g_Hres[slot*16+k] = M[k];
        }
        __syncthreads();

        float h0 = hpre[0], h1 = hpre[1], h2 = hpre[2], h3 = hpre[3];
        float hreg[8], hq = 0.f;
        #pragma unroll
        for (int u = 0; u < 8; u++) {
            float h = h0*st[0][u] + h1*st[1][u] + h2*st[2][u] + h3*st[3][u];
            hreg[u] = h; hq += h*h;
        }
        #pragma unroll
        for (int o = 16; o > 0; o >>= 1) hq += __shfl_down_sync(0xffffffffu, hq, o);
        if (lane == 0) red2[warp] = hq;
        __syncthreads();
        float sh = rsqrtf((red2[0]+red2[1]+red2[2]+red2[3]) / (float)DD + EPS_F);
        const float* snw = sw_norm_w + (size_t)e*DD;
        hf* hn = g_HN + ((size_t)e*CAP + row) * DD;
        #pragma unroll
        for (int u = 0; u < 8; u++) {
            int dd = tid + u*128;
            float v = hreg[u] * sh * snw[dd];
            hn[(dd & ~15) + posh(dd & 15)] = __float2half_rn(v);
        }
    }
}

// ---- combine res + post ----
__global__ void __launch_bounds__(128) k_out(const float* __restrict__ stream,
                                             float* __restrict__ outp)
{
    int token = blockIdx.x, b = token / TT, t = token % TT, tid = threadIdx.x;
    const float* sp0 = stream + ((size_t)b*NS*TT + t) * DD;
    float st[4][8], acc[4][8];
    #pragma unroll
    for (int i = 0; i < 4; i++)
        #pragma unroll
        for (int j = 0; j < 8; j++) {
            st[i][j] = sp0[(size_t)i*TT*DD + tid + j*128];
            acc[i][j] = 0.f;
        }
    for (int e = 0; e < EE; e++) {
        int row = g_row[token*EE + e];
        if (row < 0) continue;
        float g = g_gatev[token*EE + e];
        size_t slot = (size_t)e*CAP + row;
        float Hr[16], Hp[4];
        #pragma unroll
        for (int k = 0; k < 16; k++) Hr[k] = g_Hres[slot*16+k];
        #pragma unroll
        for (int i = 0; i < 4; i++) Hp[i] = g_Hpost[slot*4+i];
        const float* o = g_OUT + slot*DD;
        #pragma unroll
        for (int j = 0; j < 8; j++) {
            float ov = o[tid + j*128];
            #pragma unroll
            for (int i = 0; i < 4; i++) {
                float r = Hr[i*4]*st[0][j] + Hr[i*4+1]*st[1][j]
                        + Hr[i*4+2]*st[2][j] + Hr[i*4+3]*st[3][j];
                acc[i][j] += g * (r + Hp[i]*ov);
            }
        }
    }
    #pragma unroll
    for (int i = 0; i < 4; i++)
        #pragma unroll
        for (int j = 0; j < 8; j++)
            outp[((size_t)(b*NS+i)*TT + t)*DD + tid + j*128] = acc[i][j];
}

#define GSA(p, s) cudaGetSymbolAddress((void**)&p, s)

extern "C" void kernel_launch(void* const* d_in, const int* in_sizes, int n_in,
                              void* d_out, int out_size)
{
    (void)in_sizes; (void)n_in; (void)out_size;
    const float* stream   = (const float*)d_in[0];
    const float* router_w = (const float*)d_in[1];
    const float* mhc      = (const float*)d_in[2];
    const float* phi_pre  = (const float*)d_in[3];
    const float* phi_post = (const float*)d_in[4];
    const float* phi_res  = (const float*)d_in[5];
    const float* b_pre    = (const float*)d_in[6];
    const float* b_post   = (const float*)d_in[7];
    const float* b_res    = (const float*)d_in[8];
    const float* a_pre    = (const float*)d_in[9];
    const float* a_post   = (const float*)d_in[10];
    const float* a_res    = (const float*)d_in[11];
    const float* sw_nw    = (const float*)d_in[12];
    const float* wd_w     = (const float*)d_in[13];
    const float* wu_w     = (const float*)d_in[14];
    const float* gate_w   = (const float*)d_in[15];
    const float* up_w     = (const float*)d_in[16];
    const float* down_w   = (const float*)d_in[17];

    float* outp = (float*)d_out;
    float* out_gate = outp + (size_t)BB*NS*TT*DD;

    cudaFuncSetAttribute(k_gemm<0>, cudaFuncAttributeMaxDynamicSharedMemorySize, SMEM_DYN);
    cudaFuncSetAttribute(k_gemm<1>, cudaFuncAttributeMaxDynamicSharedMemorySize, SMEM_DYN);
    cudaFuncSetAttribute(k_gemm<2>, cudaFuncAttributeMaxDynamicSharedMemorySize, SMEM_DYN);
    cudaFuncSetAttribute(k_gemm<5>, cudaFuncAttributeMaxDynamicSharedMemorySize, SMEM_DYN);
    cudaFuncSetAttribute(k_gemmF, cudaFuncAttributeMaxDynamicSharedMemorySize, SMEM_F);

    hf *base, *HN, *T1, *P2, *phiW, *gt, *up, *dn, *wd, *wu;
    float *GS, *OUT, *dots;
    GSA(base, g_base); GSA(HN, g_HN); GSA(T1, g_T1); GSA(P2, g_P2);
    GSA(phiW, g_phiW); GSA(wd, g_wd); GSA(wu, g_wu); GSA(gt, g_gt);
    GSA(up, g_up); GSA(dn, g_dn);
    GSA(GS, g_GS); GSA(OUT, g_OUT); GSA(dots, g_dots);

    k_zero<<<1, 32>>>();
    k_gate<<<BT, 256>>>(stream, router_w, out_gate);
    k_packall<<<4096, 256>>>(wd_w, wu_w, gate_w, up_w, down_w,
                             mhc, phi_pre, phi_post, phi_res);

    // dots = base @ phiW^T  (N=384, K=4096)
    k_gemm<0><<<dim3(32,3,1), 256, SMEM_DYN>>>(base, NDIM, phiW, NDIM, 384, NDIM/KC,
                                               dots, (hf*)0, 384, (const float*)0, 0, BT);

    k_hn<<<BT, 128>>>(stream, b_pre, b_post, b_res, a_pre, a_post, a_res, sw_nw);

    dim3 gD(32, 8, EE);

    // T1 = silu(HN @ wd^T) -> interleaved half
    k_gemm<1><<<gD, 256, SMEM_DYN>>>(HN, DD, wd, DD, DD, DD/KC,
                                     (float*)0, T1, DD, (const float*)0, 0, -1);
    // GS = sigmoid(T1 @ wu^T) -> f32
    k_gemm<2><<<gD, 256, SMEM_DYN>>>(T1, DD, wu, DD, DD, DD/KC,
                                     GS, (hf*)0, DD, (const float*)0, 0, -1);
    // P2 = silu(HN @ gt^T) * (HN @ up^T) -> interleaved half
    k_gemmF<<<dim3(32,13,EE), 512, SMEM_F>>>(HN, gt, up, P2);
    // OUT = (P2 @ dn^T) * GS -> f32
    k_gemm<5><<<gD, 256, SMEM_DYN>>>(P2, LDP, dn, LDP, DD, LDP/KC,
                                     OUT, (hf*)0, DD, GS, DD, -1);

    k_out<<<BT, 128>>>(stream, outp);
}

// round 16
// speedup vs baseline: 1.0750x; 1.0198x over previous
#include <cuda_runtime.h>
#include <cuda_fp16.h>
#include <math.h>
#include <stdint.h>

#define BB 2
#define NS 4
#define TT 2048
#define DD 1024
#define EE 16
#define NDIM 4096
#define DFFN 1656
#define LDP 1664
#define BT (BB*TT)
#define CAP BT
#define EPS_F 1.1920929e-7f
#define RSH 80
#define KC 64
#define STG_B 40960
#define SMEM_DYN (2*STG_B)
#define STG_BF 61440
#define SMEM_F (2*STG_BF)

typedef __half hf;

// ---- device scratch ----
__device__ __align__(16) hf g_base[(size_t)BT*NDIM];
__device__ __align__(16) hf g_HN [(size_t)EE*CAP*DD];
__device__ __align__(16) hf g_T1 [(size_t)EE*CAP*DD];
__device__ __align__(16) hf g_P2 [(size_t)EE*CAP*LDP];
__device__ __align__(16) hf g_phiW[(size_t)EE*24*NDIM];
__device__ __align__(16) hf g_wd[(size_t)EE*DD*DD];
__device__ __align__(16) hf g_wu[(size_t)EE*DD*DD];
__device__ __align__(16) hf g_gt[(size_t)EE*DFFN*DD];
__device__ __align__(16) hf g_up[(size_t)EE*DFFN*DD];
__device__ __align__(16) hf g_dn[(size_t)EE*DD*LDP];
__device__ __align__(16) float g_GS [(size_t)EE*CAP*DD];
__device__ __align__(16) float g_OUT[(size_t)EE*CAP*DD];
__device__ __align__(16) float g_dots[(size_t)BT*384];
__device__ int   g_row[BT*EE];
__device__ float g_gatev[BT*EE];
__device__ int   g_cnt[EE];
__device__ int   g_tok[EE*CAP];
__device__ float g_Hpost[(size_t)EE*CAP*NS];
__device__ float g_Hres[(size_t)EE*CAP*16];

#define N1G 1048576L
#define N2G 1695744L
#define N3G 1703936L
#define N4G 98304L
#define NTOTG (2*N1G + 2*N2G + N3G + N4G)

// ---- helpers ----
__device__ __forceinline__ int posh(int n) {
    return ((n >> 1) & 3) * 4 + ((n >> 3) & 1) * 2 + (n & 1);
}
__device__ __forceinline__ void perm16(const float* s, __half2* o) {
    const int pr[8] = {0, 8, 2, 10, 4, 12, 6, 14};
    #pragma unroll
    for (int j = 0; j < 8; j++)
        o[j] = __floats2half2_rn(s[pr[j]], s[pr[j] + 1]);
}
__device__ __forceinline__ void mma16(float* c, uint32_t a0, uint32_t a1, uint32_t a2,
                                      uint32_t a3, uint32_t b0, uint32_t b1) {
    asm volatile(
        "mma.sync.aligned.m16n8k16.row.col.f32.f16.f16.f32 "
        "{%0,%1,%2,%3}, {%4,%5,%6,%7}, {%8,%9}, {%0,%1,%2,%3};"
        : "+f"(c[0]), "+f"(c[1]), "+f"(c[2]), "+f"(c[3])
        : "r"(a0), "r"(a1), "r"(a2), "r"(a3), "r"(b0), "r"(b1));
}
__device__ __forceinline__ void cp16(uint32_t s, const void* g, bool pr) {
    int b = pr ? 16 : 0;
    asm volatile("cp.async.cg.shared.global [%0], [%1], 16, %2;" :: "r"(s), "l"(g), "r"(b));
}

__global__ void k_zero() { if (threadIdx.x < EE) g_cnt[threadIdx.x] = 0; }
__global__ void __launch_bounds__(256) k_zdots() {
    int i = blockIdx.x * 256 + threadIdx.x;          // 1536 blocks x 256 x 4 floats
    float4 z = {0.f, 0.f, 0.f, 0.f};
    ((float4*)g_dots)[i] = z;
}

// ---- router gate + token rms + base emit (fused) ----
__global__ void __launch_bounds__(256) k_gate(const float* __restrict__ stream,
                                              const float* __restrict__ router_w,
                                              float* __restrict__ out_gate)
{
    int token = blockIdx.x, b = token / TT, t = token % TT, tid = threadIdx.x;
    __shared__ float route[DD], red[256], logit[EE];
    const float* sp0 = stream + ((size_t)b * NS * TT + t) * DD;
    float v[4][4];
    float ss = 0.f;
    #pragma unroll
    for (int it = 0; it < 4; it++) {
        int dd = tid + it * 256;
        float v0 = sp0[dd], v1 = sp0[(size_t)TT*DD + dd];
        float v2 = sp0[2*(size_t)TT*DD + dd], v3 = sp0[3*(size_t)TT*DD + dd];
        v[it][0] = v0; v[it][1] = v1; v[it][2] = v2; v[it][3] = v3;
        ss += v0*v0 + v1*v1 + v2*v2 + v3*v3;
        route[dd] = 0.25f * (v0 + v1 + v2 + v3);
    }
    red[tid] = ss; __syncthreads();
    for (int s = 128; s > 0; s >>= 1) { if (tid < s) red[tid] += red[tid+s]; __syncthreads(); }
    float srms = rsqrtf(red[0] / (float)NDIM + EPS_F);

    hf* dst = g_base + (size_t)token * NDIM;
    #pragma unroll
    for (int it = 0; it < 4; it++) {
        int dd = tid + it * 256;
        #pragma unroll
        for (int i = 0; i < 4; i++) {
            int j = i * 1024 + dd;
            dst[(j & ~15) | posh(j & 15)] = __float2half_rn(v[it][i] * srms);
        }
    }

    int warp = tid >> 5, lane = tid & 31;
    for (int e = warp; e < EE; e += 8) {
        const float* rw = router_w + (size_t)e * DD;
        float acc = 0.f;
        for (int dd = lane; dd < DD; dd += 32) acc += route[dd] * rw[dd];
        #pragma unroll
        for (int o = 16; o > 0; o >>= 1) acc += __shfl_down_sync(0xffffffffu, acc, o);
        if (lane == 0) logit[e] = acc;
    }
    __syncthreads();
    if (tid == 0) {
        float p[EE], mx = -1e30f;
        #pragma unroll
        for (int e = 0; e < EE; e++) mx = fmaxf(mx, logit[e]);
        float sum = 0.f;
        #pragma unroll
        for (int e = 0; e < EE; e++) { p[e] = expf(logit[e] - mx); sum += p[e]; }
        float inv = 1.f / sum;
        #pragma unroll
        for (int e = 0; e < EE; e++) p[e] *= inv;
        int ord[EE];
        #pragma unroll
        for (int e = 0; e < EE; e++) ord[e] = e;
        for (int i = 1; i < EE; i++) {
            int oi = ord[i]; float pi = p[oi]; int j = i - 1;
            while (j >= 0 && p[ord[j]] < pi) { ord[j+1] = ord[j]; j--; }
            ord[j+1] = oi;
        }
        float cum = 0.f, gate[EE];
        #pragma unroll
        for (int e = 0; e < EE; e++) gate[e] = 0.f;
        for (int r = 0; r < EE; r++) {
            int e = ord[r];
            if ((r == 0) || (cum < 0.8f && r < 4)) gate[e] = p[e];
            cum += p[e];
        }
        for (int e = 0; e < EE; e++) {
            float g = gate[e];
            out_gate[(size_t)token*EE + e] = g;
            g_gatev[token*EE + e] = g;
            int row = -1;
            if (g > 0.f) { row = atomicAdd(&g_cnt[e], 1); g_tok[e*CAP + row] = token; }
            g_row[token*EE + e] = row;
        }
    }
}

// ---- merged weight pack ----
__device__ __forceinline__ void packgrp(const float* p, hf* q) {
    float sv[16];
    #pragma unroll
    for (int c = 0; c < 4; c++) {
        float4 v = *(const float4*)(p + c*4);
        sv[c*4+0] = v.x; sv[c*4+1] = v.y; sv[c*4+2] = v.z; sv[c*4+3] = v.w;
    }
    __half2 o[8]; perm16(sv, o);
    *(uint4*)q = *(uint4*)o;
    *(uint4*)(q + 8) = *(uint4*)(o + 4);
}
__global__ void __launch_bounds__(256) k_packall(const float* __restrict__ wd_w,
                                                 const float* __restrict__ wu_w,
                                                 const float* __restrict__ gate_w,
                                                 const float* __restrict__ up_w,
                                                 const float* __restrict__ down_w,
                                                 const float* __restrict__ mhc,
                                                 const float* __restrict__ pw,
                                                 const float* __restrict__ ow,
                                                 const float* __restrict__ rw)
{
    long g0 = (long)blockIdx.x * 256 + threadIdx.x;
    long stride = (long)gridDim.x * 256;
    for (long g = g0; g < NTOTG; g += stride) {
        if (g < 2*N1G) {
            long l = (g < N1G) ? g : g - N1G;
            const float* src = (g < N1G) ? wd_w : wu_w;
            hf* dst = (g < N1G) ? g_wd : g_wu;
            long row = l >> 6; int gi = (int)(l & 63);
            packgrp(src + row * DD + gi * 16, dst + l * 16);
        } else if (g < 2*N1G + 2*N2G) {
            long l = g - 2*N1G;
            const float* src = (l < N2G) ? gate_w : up_w;
            hf* dst = (l < N2G) ? g_gt : g_up;
            if (l >= N2G) l -= N2G;
            long row = l >> 6; int gi = (int)(l & 63);
            packgrp(src + row * DD + gi * 16, dst + l * 16);
        } else if (g < 2*N1G + 2*N2G + N3G) {
            long l = g - 2*N1G - 2*N2G;
            long row = l / 104; int gi = (int)(l - row * 104);
            hf* q = g_dn + l * 16;
            if (gi * 16 + 16 <= DFFN) {
                packgrp(down_w + row * DFFN + gi * 16, q);
            } else {
                float sv[16];
                #pragma unroll
                for (int j = 0; j < 16; j++) {
                    int k = gi * 16 + j;
                    sv[j] = (k < DFFN) ? down_w[row * DFFN + k] : 0.f;
                }
                __half2 o[8]; perm16(sv, o);
                *(uint4*)q = *(uint4*)o;
                *(uint4*)(q + 8) = *(uint4*)(o + 4);
            }
        } else {
            long l = g - 2*N1G - 2*N2G - N3G;
            int e = (int)(l / 6144);
            int rem = (int)(l - (long)e * 6144);
            int r = rem >> 8;
            int j0 = (rem & 255) * 16;
            const float* wsrc;
            if (r < 4)      wsrc = pw + ((size_t)e*4 + r)*NDIM + j0;
            else if (r < 8) wsrc = ow + ((size_t)e*4 + (r-4))*NDIM + j0;
            else            wsrc = rw + ((size_t)e*16 + (r-8))*NDIM + j0;
            const float* nsrc = mhc + (size_t)e*NDIM + j0;
            float sv[16];
            #pragma unroll
            for (int q2 = 0; q2 < 4; q2++) {
                float4 w = *(const float4*)(wsrc + q2*4);
                float4 n = *(const float4*)(nsrc + q2*4);
                sv[q2*4+0] = w.x*n.x; sv[q2*4+1] = w.y*n.y;
                sv[q2*4+2] = w.z*n.z; sv[q2*4+3] = w.w*n.w;
            }
            __half2 o[8]; perm16(sv, o);
            hf* q = g_phiW + l * 16;
            *(uint4*)q = *(uint4*)o;
            *(uint4*)(q + 8) = *(uint4*)(o + 4);
        }
    }
}

// ---- fp16 GEMM 128x128, 2 CTA/SM ----
// MODE 0 raw->Cf, 1 silu->Ch, 2 sigm->Cf, 5 mulAux->Cf, 6 atomicAdd->Cf (splitK x3)
template <int MODE>
__global__ void __launch_bounds__(256, 2) k_gemm(
    const hf* __restrict__ A, int lda,
    const hf* __restrict__ W, int ldw, int Ntot, int KT,
    float* __restrict__ Cf, hf* __restrict__ Ch, int ldc,
    const float* __restrict__ Aux, int ldaux, int cntOv)
{
    extern __shared__ hf smh[];
    int e = blockIdx.z;
    int kt_begin = 0, kt_end = KT;
    if (MODE == 6) {
        int per = (KT + 2) / 3;
        kt_begin = blockIdx.z * per;
        kt_end = min(KT, kt_begin + per);
        e = 0;
    }
    int cnt = (cntOv >= 0) ? cntOv : g_cnt[e];
    int m0 = blockIdx.x * 128;
    if (m0 >= cnt) return;
    int n0 = blockIdx.y * 128;

    A += (size_t)e * CAP * lda;
    W += (size_t)e * Ntot * ldw;
    size_t co = (size_t)e * CAP * ldc;
    if (Cf) Cf += co;
    if (Ch) Ch += co;
    if (Aux) Aux += (size_t)e * CAP * ldaux;

    uint32_t sb = (uint32_t)__cvta_generic_to_shared(smh);
    int tid = threadIdx.x, warp = tid >> 5, lane = tid & 31;
    int wm = warp >> 1, wn = warp & 1;
    int qr = lane >> 2, qc = lane & 3;

    float acc[2][8][4];
    #pragma unroll
    for (int mt = 0; mt < 2; mt++)
        #pragma unroll
        for (int nt = 0; nt < 8; nt++)
            #pragma unroll
            for (int q = 0; q < 4; q++) acc[mt][nt][q] = 0.f;

    auto load_stage = [&](int kt, int stg) {
        int k0 = kt * KC;
        #pragma unroll
        for (int s4 = 0; s4 < 4; s4++) {
            int f = tid + s4*256, r = f >> 3, c = f & 7;
            cp16(sb + stg*STG_B + r*160 + c*16, A + (size_t)(m0 + r)*lda + k0 + c*8, true);
        }
        #pragma unroll
        for (int s4 = 0; s4 < 4; s4++) {
            int f = tid + s4*256, r = f >> 3, c = f & 7;
            bool pr = (n0 + r) < Ntot;
            const hf* gp = W + (size_t)(n0 + r)*ldw + k0 + c*8;
            cp16(sb + stg*STG_B + 20480 + r*160 + c*16, pr ? gp : W, pr);
        }
        asm volatile("cp.async.commit_group;");
    };

    int nk = kt_end - kt_begin;
    load_stage(kt_begin, 0);

    for (int i = 0; i < nk; i++) {
        if (i + 1 < nk) load_stage(kt_begin + i + 1, (i + 1) & 1);
        if (i + 1 < nk) asm volatile("cp.async.wait_group 1;");
        else            asm volatile("cp.async.wait_group 0;");
        __syncthreads();

        int stg = i & 1;
        const hf* Asm = smh + stg * (STG_B/2);
        const hf* Bsm = Asm + 10240;

        #pragma unroll
        for (int ks = 0; ks < 4; ks++) {
            int kb = ks * 16 + qc * 4;
            uint2 a0 = *(const uint2*)(Asm + (wm*32 + qr)*RSH + kb);
            uint2 a1 = *(const uint2*)(Asm + (wm*32 + qr + 8)*RSH + kb);
            uint2 a2 = *(const uint2*)(Asm + (wm*32 + 16 + qr)*RSH + kb);
            uint2 a3 = *(const uint2*)(Asm + (wm*32 + 16 + qr + 8)*RSH + kb);
            const hf* bp = Bsm + (wn*64 + qr)*RSH + kb;
            #pragma unroll
            for (int nt = 0; nt < 8; nt++) {
                uint2 bb = *(const uint2*)(bp + nt*8*RSH);
                mma16(acc[0][nt], a0.x, a1.x, a0.y, a1.y, bb.x, bb.y);
                mma16(acc[1][nt], a2.x, a3.x, a2.y, a3.y, bb.x, bb.y);
            }
        }
        __syncthreads();
    }

    #pragma unroll
    for (int mt = 0; mt < 2; mt++) {
        #pragma unroll
        for (int nt = 0; nt < 8; nt++) {
            int n = n0 + wn*64 + nt*8 + qc*2;
            #pragma unroll
            for (int half = 0; half < 2; half++) {
                int m = m0 + wm*32 + mt*16 + qr + half*8;
                if (m >= cnt) continue;
                float v0 = acc[mt][nt][half*2], v1 = acc[mt][nt][half*2 + 1];
                if (MODE == 0) {
                    if (n < Ntot) {
                        float2 s2 = {v0, v1};
                        *(float2*)(Cf + (size_t)m * ldc + n) = s2;
                    }
                } else if (MODE == 6) {
                    if (n < Ntot) {
                        atomicAdd(Cf + (size_t)m * ldc + n, v0);
                        atomicAdd(Cf + (size_t)m * ldc + n + 1, v1);
                    }
                } else if (MODE == 2) {
                    if (n < Ntot) {
                        float2 s2 = {1.f/(1.f+expf(-v0)), 1.f/(1.f+expf(-v1))};
                        *(float2*)(Cf + (size_t)m * ldc + n) = s2;
                    }
                } else if (MODE == 5) {
                    if (n < Ntot) {
                        float2 s2 = {v0 * Aux[(size_t)m*ldaux + n], v1 * Aux[(size_t)m*ldaux + n + 1]};
                        *(float2*)(Cf + (size_t)m * ldc + n) = s2;
                    }
                } else {
                    if (n < Ntot) {
                        float x0 = v0/(1.f+expf(-v0)), x1 = v1/(1.f+expf(-v1));
                        size_t rowo = (size_t)m * ldc + (n & ~15);
                        *(__half2*)(Ch + rowo + posh(n & 15)) = __floats2half2_rn(x0, x1);
                    }
                }
            }
        }
    }
}

// ---- fused gate/up fp16 GEMM ----
__global__ void __launch_bounds__(512, 1) k_gemmF(
    const hf* __restrict__ A,
    const hf* __restrict__ Wg, const hf* __restrict__ Wu,
    hf* __restrict__ Ch)
{
    extern __shared__ hf smh[];
    int e = blockIdx.z;
    int cnt = g_cnt[e];
    int m0 = blockIdx.x * 128;
    if (m0 >= cnt) return;
    int n0 = blockIdx.y * 128;

    A  += (size_t)e * CAP * DD;
    Wg += (size_t)e * DFFN * DD;
    Wu += (size_t)e * DFFN * DD;
    Ch += (size_t)e * CAP * LDP;

    uint32_t sb = (uint32_t)__cvta_generic_to_shared(smh);
    int tid = threadIdx.x, warp = tid >> 5, lane = tid & 31;
    int wm = warp >> 3, wn = warp & 7;
    int qr = lane >> 2, qc = lane & 3;

    float accG[4][2][4], accU[4][2][4];
    #pragma unroll
    for (int mt = 0; mt < 4; mt++)
        #pragma unroll
        for (int nt = 0; nt < 2; nt++)
            #pragma unroll
            for (int q = 0; q < 4; q++) { accG[mt][nt][q] = 0.f; accU[mt][nt][q] = 0.f; }

    auto load_stage = [&](int kt, int stg) {
        int k0 = kt * KC;
        #pragma unroll
        for (int i = 0; i < 6; i++) {
            int f = tid + i*512, r = f >> 3, c = f & 7;
            const hf* gp; bool pr = true;
            if (r < 128) {
                gp = A + (size_t)(m0 + r)*DD + k0 + c*8;
            } else if (r < 256) {
                int nr = n0 + r - 128; pr = nr < DFFN;
                gp = pr ? (Wg + (size_t)nr*DD + k0 + c*8) : A;
            } else {
                int nr = n0 + r - 256; pr = nr < DFFN;
                gp = pr ? (Wu + (size_t)nr*DD + k0 + c*8) : A;
            }
            cp16(sb + stg*STG_BF + r*160 + c*16, gp, pr);
        }
        asm volatile("cp.async.commit_group;");
    };

    const int KT = DD / KC;
    load_stage(0, 0);

    for (int kt = 0; kt < KT; kt++) {
        if (kt + 1 < KT) load_stage(kt + 1, (kt + 1) & 1);
        if (kt + 1 < KT) asm volatile("cp.async.wait_group 1;");
        else             asm volatile("cp.async.wait_group 0;");
        __syncthreads();

        int stg = kt & 1;
        const hf* Asm = smh + stg * (STG_BF/2);
        const hf* Gsm = Asm + 10240;
        const hf* Usm = Asm + 20480;

        #pragma unroll
        for (int ks = 0; ks < 4; ks++) {
            int kb = ks * 16 + qc * 4;
            uint2 al[4], ah[4];
            #pragma unroll
            for (int mt = 0; mt < 4; mt++) {
                al[mt] = *(const uint2*)(Asm + (wm*64 + mt*16 + qr)*RSH + kb);
                ah[mt] = *(const uint2*)(Asm + (wm*64 + mt*16 + qr + 8)*RSH + kb);
            }
            #pragma unroll
            for (int nt = 0; nt < 2; nt++) {
                int br = (wn*16 + nt*8 + qr)*RSH + kb;
                uint2 bg = *(const uint2*)(Gsm + br);
                uint2 bu = *(const uint2*)(Usm + br);
                #pragma unroll
                for (int mt = 0; mt < 4; mt++) {
                    mma16(accG[mt][nt], al[mt].x, ah[mt].x, al[mt].y, ah[mt].y, bg.x, bg.y);
                    mma16(accU[mt][nt], al[mt].x, ah[mt].x, al[mt].y, ah[mt].y, bu.x, bu.y);
                }
            }
        }
        __syncthreads();
    }

    #pragma unroll
    for (int mt = 0; mt < 4; mt++) {
        #pragma unroll
        for (int nt = 0; nt < 2; nt++) {
            int n = n0 + wn*16 + nt*8 + qc*2;
            #pragma unroll
            for (int half = 0; half < 2; half++) {
                int m = m0 + wm*64 + mt*16 + qr + half*8;
                if (m >= cnt) continue;
                size_t rowo = (size_t)m * LDP + (n & ~15);
                int p0 = posh(n & 15);
                if (n < DFFN) {
                    float gv0 = accG[mt][nt][half*2], gv1 = accG[mt][nt][half*2 + 1];
                    float uv0 = accU[mt][nt][half*2], uv1 = accU[mt][nt][half*2 + 1];
                    float x0 = (gv0/(1.f+expf(-gv0))) * uv0;
                    float x1 = (gv1/(1.f+expf(-gv1))) * uv1;
                    *(__half2*)(Ch + rowo + p0) = __floats2half2_rn(x0, x1);
                } else if (n < LDP) {
                    *(__half2*)(Ch + rowo + p0) = __floats2half2_rn(0.f, 0.f);
                }
            }
        }
    }
}

// ---- per-token: gates, sinkhorn, h, hn ----
__global__ void __launch_bounds__(128) k_hn(const float* __restrict__ stream,
                                            const float* __restrict__ b_pre,
                                            const float* __restrict__ b_post,
                                            const float* __restrict__ b_res,
                                            const float* __restrict__ alpha_pre,
                                            const float* __restrict__ alpha_post,
                                            const float* __restrict__ alpha_res,
                                            const float* __restrict__ sw_norm_w)
{
    int token = blockIdx.x, b = token / TT, t = token % TT, tid = threadIdx.x;
    __shared__ float hpre[NS], red2[4];
    int lane = tid & 31, warp = tid >> 5;

    const float* sp0 = stream + ((size_t)b*NS*TT + t) * DD;
    float st[4][8];
    #pragma unroll
    for (int i = 0; i < 4; i++)
        #pragma unroll
        for (int u = 0; u < 8; u++)
            st[i][u] = sp0[(size_t)i*TT*DD + tid + u*128];

    for (int e = 0; e < EE; e++) {
        int row = g_row[token*EE + e];
        if (row < 0) continue;
        __syncthreads();
        if (tid == 0) {
            const float* d = g_dots + (size_t)token*384 + e*24;
            size_t slot = (size_t)e*CAP + row;
            float ap = alpha_pre[e], ao = alpha_post[e], ar = alpha_res[e];
            #pragma unroll
            for (int i = 0; i < NS; i++)
                hpre[i] = 1.f / (1.f + expf(-(ap*d[i] + b_pre[e*NS+i])));
            #pragma unroll
            for (int i = 0; i < NS; i++)
                g_Hpost[slot*NS+i] = 2.f / (1.f + expf(-(ao*d[4+i] + b_post[e*NS+i])));
            float M[16];
            #pragma unroll
            for (int k = 0; k < 16; k++) M[k] = expf(ar*d[8+k] + b_res[e*16+k]);
            for (int it = 0; it < 6; it++) {
                #pragma unroll
                for (int i = 0; i < 4; i++) {
                    float ir = 1.f / (M[i*4]+M[i*4+1]+M[i*4+2]+M[i*4+3]);
                    M[i*4]*=ir; M[i*4+1]*=ir; M[i*4+2]*=ir; M[i*4+3]*=ir;
                }
                #pragma unroll
                for (int j = 0; j < 4; j++) {
                    float ic = 1.f / (M[j]+M[4+j]+M[8+j]+M[12+j]);
                    M[j]*=ic; M[4+j]*=ic; M[8+j]*=ic; M[12+j]*=ic;
                }
            }
            #pragma unroll
            for (int k = 0; k < 16; k++) g_Hres[slot*16+k] = M[k];
        }
        __syncthreads();

        float h0 = hpre[0], h1 = hpre[1], h2 = hpre[2], h3 = hpre[3];
        float hreg[8], hq = 0.f;
        #pragma unroll
        for (int u = 0; u < 8; u++) {
            float h = h0*st[0][u] + h1*st[1][u] + h2*st[2][u] + h3*st[3][u];
            hreg[u] = h; hq += h*h;
        }
        #pragma unroll
        for (int o = 16; o > 0; o >>= 1) hq += __shfl_down_sync(0xffffffffu, hq, o);
        if (lane == 0) red2[warp] = hq;
        __syncthreads();
        float sh = rsqrtf((red2[0]+red2[1]+red2[2]+red2[3]) / (float)DD + EPS_F);
        const float* snw = sw_norm_w + (size_t)e*DD;
        hf* hn = g_HN + ((size_t)e*CAP + row) * DD;
        #pragma unroll
        for (int u = 0; u < 8; u++) {
            int dd = tid + u*128;
            float v = hreg[u] * sh * snw[dd];
            hn[(dd & ~15) + posh(dd & 15)] = __float2half_rn(v);
        }
    }
}

// ---- combine res + post ----
__global__ void __launch_bounds__(128) k_out(const float* __restrict__ stream,
                                             float* __restrict__ outp)
{
    int token = blockIdx.x, b = token / TT, t = token % TT, tid = threadIdx.x;
    const float* sp0 = stream + ((size_t)b*NS*TT + t) * DD;
    float st[4][8], acc[4][8];
    #pragma unroll
    for (int i = 0; i < 4; i++)
        #pragma unroll
        for (int j = 0; j < 8; j++) {
            st[i][j] = sp0[(size_t)i*TT*DD + tid + j*128];
            acc[i][j] = 0.f;
        }
    for (int e = 0; e < EE; e++) {
        int row = g_row[token*EE + e];
        if (row < 0) continue;
        float g = g_gatev[token*EE + e];
        size_t slot = (size_t)e*CAP + row;
        float Hr[16], Hp[4];
        #pragma unroll
        for (int k = 0; k < 16; k++) Hr[k] = g_Hres[slot*16+k];
        #pragma unroll
        for (int i = 0; i < 4; i++) Hp[i] = g_Hpost[slot*4+i];
        const float* o = g_OUT + slot*DD;
        #pragma unroll
        for (int j = 0; j < 8; j++) {
            float ov = o[tid + j*128];
            #pragma unroll
            for (int i = 0; i < 4; i++) {
                float r = Hr[i*4]*st[0][j] + Hr[i*4+1]*st[1][j]
                        + Hr[i*4+2]*st[2][j] + Hr[i*4+3]*st[3][j];
                acc[i][j] += g * (r + Hp[i]*ov);
            }
        }
    }
    #pragma unroll
    for (int i = 0; i < 4; i++)
        #pragma unroll
        for (int j = 0; j < 8; j++)
            outp[((size_t)(b*NS+i)*TT + t)*DD + tid + j*128] = acc[i][j];
}

#define GSA(p, s) cudaGetSymbolAddress((void**)&p, s)

extern "C" void kernel_launch(void* const* d_in, const int* in_sizes, int n_in,
                              void* d_out, int out_size)
{
    (void)in_sizes; (void)n_in; (void)out_size;
    const float* stream   = (const float*)d_in[0];
    const float* router_w = (const float*)d_in[1];
    const float* mhc      = (const float*)d_in[2];
    const float* phi_pre  = (const float*)d_in[3];
    const float* phi_post = (const float*)d_in[4];
    const float* phi_res  = (const float*)d_in[5];
    const float* b_pre    = (const float*)d_in[6];
    const float* b_post   = (const float*)d_in[7];
    const float* b_res    = (const float*)d_in[8];
    const float* a_pre    = (const float*)d_in[9];
    const float* a_post   = (const float*)d_in[10];
    const float* a_res    = (const float*)d_in[11];
    const float* sw_nw    = (const float*)d_in[12];
    const float* wd_w     = (const float*)d_in[13];
    const float* wu_w     = (const float*)d_in[14];
    const float* gate_w   = (const float*)d_in[15];
    const float* up_w     = (const float*)d_in[16];
    const float* down_w   = (const float*)d_in[17];

    float* outp = (float*)d_out;
    float* out_gate = outp + (size_t)BB*NS*TT*DD;

    cudaFuncSetAttribute(k_gemm<1>, cudaFuncAttributeMaxDynamicSharedMemorySize, SMEM_DYN);
    cudaFuncSetAttribute(k_gemm<2>, cudaFuncAttributeMaxDynamicSharedMemorySize, SMEM_DYN);
    cudaFuncSetAttribute(k_gemm<5>, cudaFuncAttributeMaxDynamicSharedMemorySize, SMEM_DYN);
    cudaFuncSetAttribute(k_gemm<6>, cudaFuncAttributeMaxDynamicSharedMemorySize, SMEM_DYN);
    cudaFuncSetAttribute(k_gemmF, cudaFuncAttributeMaxDynamicSharedMemorySize, SMEM_F);

    hf *base, *HN, *T1, *P2, *phiW, *gt, *up, *dn, *wd, *wu;
    float *GS, *OUT, *dots;
    GSA(base, g_base); GSA(HN, g_HN); GSA(T1, g_T1); GSA(P2, g_P2);
    GSA(phiW, g_phiW); GSA(wd, g_wd); GSA(wu, g_wu); GSA(gt, g_gt);
    GSA(up, g_up); GSA(dn, g_dn);
    GSA(GS, g_GS); GSA(OUT, g_OUT); GSA(dots, g_dots);

    k_zero<<<1, 32>>>();
    k_zdots<<<(BT*384/4)/256, 256>>>();
    k_gate<<<BT, 256>>>(stream, router_w, out_gate);
    k_packall<<<4096, 256>>>(wd_w, wu_w, gate_w, up_w, down_w,
                             mhc, phi_pre, phi_post, phi_res);

    // dots = base @ phiW^T  (N=384, K=4096), split-K x3 with atomic accumulation
    k_gemm<6><<<dim3(32,3,3), 256, SMEM_DYN>>>(base, NDIM, phiW, NDIM, 384, NDIM/KC,
                                               dots, (hf*)0, 384, (const float*)0, 0, BT);

    k_hn<<<BT, 128>>>(stream, b_pre, b_post, b_res, a_pre, a_post, a_res, sw_nw);

    dim3 gD(32, 8, EE);

    // T1 = silu(HN @ wd^T) -> interleaved half
    k_gemm<1><<<gD, 256, SMEM_DYN>>>(HN, DD, wd, DD, DD, DD/KC,
                                     (float*)0, T1, DD, (const float*)0, 0, -1);
    // GS = sigmoid(T1 @ wu^T) -> f32
    k_gemm<2><<<gD, 256, SMEM_DYN>>>(T1, DD, wu, DD, DD, DD/KC,
                                     GS, (hf*)0, DD, (const float*)0, 0, -1);
    // P2 = silu(HN @ gt^T) * (HN @ up^T) -> interleaved half
    k_gemmF<<<dim3(32,13,EE), 512, SMEM_F>>>(HN, gt, up, P2);
    // OUT = (P2 @ dn^T) * GS -> f32
    k_gemm<5><<<gD, 256, SMEM_DYN>>>(P2, LDP, dn, LDP, DD, LDP/KC,
                                     OUT, (hf*)0, DD, GS, DD, -1);

    k_out<<<BT, 128>>>(stream, outp);
}

// round 17
// speedup vs baseline: 1.1067x; 1.0295x over previous
#include <cuda_runtime.h>
#include <cuda_fp16.h>
#include <math.h>
#include <stdint.h>

#define BB 2
#define NS 4
#define TT 2048
#define DD 1024
#define EE 16
#define NDIM 4096
#define DFFN 1656
#define LDP 1664
#define BT (BB*TT)
#define CAP BT
#define EPS_F 1.1920929e-7f
#define RSH 80
#define KC 64
#define STG_B 40960
#define SMEM_DYN (2*STG_B)
#define SMEM_F (2*STG_B)

typedef __half hf;

// ---- device scratch ----
__device__ __align__(16) hf g_base[(size_t)BT*NDIM];
__device__ __align__(16) hf g_HN [(size_t)EE*CAP*DD];
__device__ __align__(16) hf g_T1 [(size_t)EE*CAP*DD];
__device__ __align__(16) hf g_P2 [(size_t)EE*CAP*LDP];
__device__ __align__(16) hf g_phiW[(size_t)EE*24*NDIM];
__device__ __align__(16) hf g_wd[(size_t)EE*DD*DD];
__device__ __align__(16) hf g_wu[(size_t)EE*DD*DD];
__device__ __align__(16) hf g_gt[(size_t)EE*DFFN*DD];
__device__ __align__(16) hf g_up[(size_t)EE*DFFN*DD];
__device__ __align__(16) hf g_dn[(size_t)EE*DD*LDP];
__device__ __align__(16) float g_GS [(size_t)EE*CAP*DD];
__device__ __align__(16) float g_OUT[(size_t)EE*CAP*DD];
__device__ __align__(16) float g_dots[(size_t)BT*384];
__device__ int   g_row[BT*EE];
__device__ float g_gatev[BT*EE];
__device__ int   g_cnt[EE];
__device__ int   g_tok[EE*CAP];
__device__ float g_Hpost[(size_t)EE*CAP*NS];
__device__ float g_Hres[(size_t)EE*CAP*16];

#define N1G 1048576L
#define N2G 1695744L
#define N3G 1703936L
#define N4G 98304L
#define NTOTG (2*N1G + 2*N2G + N3G + N4G)

// ---- helpers ----
__device__ __forceinline__ int posh(int n) {
    return ((n >> 1) & 3) * 4 + ((n >> 3) & 1) * 2 + (n & 1);
}
__device__ __forceinline__ void perm16(const float* s, __half2* o) {
    const int pr[8] = {0, 8, 2, 10, 4, 12, 6, 14};
    #pragma unroll
    for (int j = 0; j < 8; j++)
        o[j] = __floats2half2_rn(s[pr[j]], s[pr[j] + 1]);
}
__device__ __forceinline__ void mma16(float* c, uint32_t a0, uint32_t a1, uint32_t a2,
                                      uint32_t a3, uint32_t b0, uint32_t b1) {
    asm volatile(
        "mma.sync.aligned.m16n8k16.row.col.f32.f16.f16.f32 "
        "{%0,%1,%2,%3}, {%4,%5,%6,%7}, {%8,%9}, {%0,%1,%2,%3};"
        : "+f"(c[0]), "+f"(c[1]), "+f"(c[2]), "+f"(c[3])
        : "r"(a0), "r"(a1), "r"(a2), "r"(a3), "r"(b0), "r"(b1));
}
__device__ __forceinline__ void cp16(uint32_t s, const void* g, bool pr) {
    int b = pr ? 16 : 0;
    asm volatile("cp.async.cg.shared.global [%0], [%1], 16, %2;" :: "r"(s), "l"(g), "r"(b));
}

__global__ void k_zero() { if (threadIdx.x < EE) g_cnt[threadIdx.x] = 0; }
__global__ void __launch_bounds__(256) k_zdots() {
    int i = blockIdx.x * 256 + threadIdx.x;
    float4 z = {0.f, 0.f, 0.f, 0.f};
    ((float4*)g_dots)[i] = z;
}

// ---- router gate + token rms + base emit (fused) ----
__global__ void __launch_bounds__(256) k_gate(const float* __restrict__ stream,
                                              const float* __restrict__ router_w,
                                              float* __restrict__ out_gate)
{
    int token = blockIdx.x, b = token / TT, t = token % TT, tid = threadIdx.x;
    __shared__ float route[DD], red[256], logit[EE];
    const float* sp0 = stream + ((size_t)b * NS * TT + t) * DD;
    float v[4][4];
    float ss = 0.f;
    #pragma unroll
    for (int it = 0; it < 4; it++) {
        int dd = tid + it * 256;
        float v0 = sp0[dd], v1 = sp0[(size_t)TT*DD + dd];
        float v2 = sp0[2*(size_t)TT*DD + dd], v3 = sp0[3*(size_t)TT*DD + dd];
        v[it][0] = v0; v[it][1] = v1; v[it][2] = v2; v[it][3] = v3;
        ss += v0*v0 + v1*v1 + v2*v2 + v3*v3;
        route[dd] = 0.25f * (v0 + v1 + v2 + v3);
    }
    red[tid] = ss; __syncthreads();
    for (int s = 128; s > 0; s >>= 1) { if (tid < s) red[tid] += red[tid+s]; __syncthreads(); }
    float srms = rsqrtf(red[0] / (float)NDIM + EPS_F);

    hf* dst = g_base + (size_t)token * NDIM;
    #pragma unroll
    for (int it = 0; it < 4; it++) {
        int dd = tid + it * 256;
        #pragma unroll
        for (int i = 0; i < 4; i++) {
            int j = i * 1024 + dd;
            dst[(j & ~15) | posh(j & 15)] = __float2half_rn(v[it][i] * srms);
        }
    }

    int warp = tid >> 5, lane = tid & 31;
    for (int e = warp; e < EE; e += 8) {
        const float* rw = router_w + (size_t)e * DD;
        float acc = 0.f;
        for (int dd = lane; dd < DD; dd += 32) acc += route[dd] * rw[dd];
        #pragma unroll
        for (int o = 16; o > 0; o >>= 1) acc += __shfl_down_sync(0xffffffffu, acc, o);
        if (lane == 0) logit[e] = acc;
    }
    __syncthreads();
    if (tid == 0) {
        float p[EE], mx = -1e30f;
        #pragma unroll
        for (int e = 0; e < EE; e++) mx = fmaxf(mx, logit[e]);
        float sum = 0.f;
        #pragma unroll
        for (int e = 0; e < EE; e++) { p[e] = expf(logit[e] - mx); sum += p[e]; }
        float inv = 1.f / sum;
        #pragma unroll
        for (int e = 0; e < EE; e++) p[e] *= inv;
        int ord[EE];
        #pragma unroll
        for (int e = 0; e < EE; e++) ord[e] = e;
        for (int i = 1; i < EE; i++) {
            int oi = ord[i]; float pi = p[oi]; int j = i - 1;
            while (j >= 0 && p[ord[j]] < pi) { ord[j+1] = ord[j]; j--; }
            ord[j+1] = oi;
        }
        float cum = 0.f, gate[EE];
        #pragma unroll
        for (int e = 0; e < EE; e++) gate[e] = 0.f;
        for (int r = 0; r < EE; r++) {
            int e = ord[r];
            if ((r == 0) || (cum < 0.8f && r < 4)) gate[e] = p[e];
            cum += p[e];
        }
        for (int e = 0; e < EE; e++) {
            float g = gate[e];
            out_gate[(size_t)token*EE + e] = g;
            g_gatev[token*EE + e] = g;
            int row = -1;
            if (g > 0.f) { row = atomicAdd(&g_cnt[e], 1); g_tok[e*CAP + row] = token; }
            g_row[token*EE + e] = row;
        }
    }
}

// ---- merged weight pack ----
__device__ __forceinline__ void packgrp(const float* p, hf* q) {
    float sv[16];
    #pragma unroll
    for (int c = 0; c < 4; c++) {
        float4 v = *(const float4*)(p + c*4);
        sv[c*4+0] = v.x; sv[c*4+1] = v.y; sv[c*4+2] = v.z; sv[c*4+3] = v.w;
    }
    __half2 o[8]; perm16(sv, o);
    *(uint4*)q = *(uint4*)o;
    *(uint4*)(q + 8) = *(uint4*)(o + 4);
}
__global__ void __launch_bounds__(256) k_packall(const float* __restrict__ wd_w,
                                                 const float* __restrict__ wu_w,
                                                 const float* __restrict__ gate_w,
                                                 const float* __restrict__ up_w,
                                                 const float* __restrict__ down_w,
                                                 const float* __restrict__ mhc,
                                                 const float* __restrict__ pw,
                                                 const float* __restrict__ ow,
                                                 const float* __restrict__ rw)
{
    long g0 = (long)blockIdx.x * 256 + threadIdx.x;
    long stride = (long)gridDim.x * 256;
    for (long g = g0; g < NTOTG; g += stride) {
        if (g < 2*N1G) {
            long l = (g < N1G) ? g : g - N1G;
            const float* src = (g < N1G) ? wd_w : wu_w;
            hf* dst = (g < N1G) ? g_wd : g_wu;
            long row = l >> 6; int gi = (int)(l & 63);
            packgrp(src + row * DD + gi * 16, dst + l * 16);
        } else if (g < 2*N1G + 2*N2G) {
            long l = g - 2*N1G;
            const float* src = (l < N2G) ? gate_w : up_w;
            hf* dst = (l < N2G) ? g_gt : g_up;
            if (l >= N2G) l -= N2G;
            long row = l >> 6; int gi = (int)(l & 63);
            packgrp(src + row * DD + gi * 16, dst + l * 16);
        } else if (g < 2*N1G + 2*N2G + N3G) {
            long l = g - 2*N1G - 2*N2G;
            long row = l / 104; int gi = (int)(l - row * 104);
            hf* q = g_dn + l * 16;
            if (gi * 16 + 16 <= DFFN) {
                packgrp(down_w + row * DFFN + gi * 16, q);
            } else {
                float sv[16];
                #pragma unroll
                for (int j = 0; j < 16; j++) {
                    int k = gi * 16 + j;
                    sv[j] = (k < DFFN) ? down_w[row * DFFN + k] : 0.f;
                }
                __half2 o[8]; perm16(sv, o);
                *(uint4*)q = *(uint4*)o;
                *(uint4*)(q + 8) = *(uint4*)(o + 4);
            }
        } else {
            long l = g - 2*N1G - 2*N2G - N3G;
            int e = (int)(l / 6144);
            int rem = (int)(l - (long)e * 6144);
            int r = rem >> 8;
            int j0 = (rem & 255) * 16;
            const float* wsrc;
            if (r < 4)      wsrc = pw + ((size_t)e*4 + r)*NDIM + j0;
            else if (r < 8) wsrc = ow + ((size_t)e*4 + (r-4))*NDIM + j0;
            else            wsrc = rw + ((size_t)e*16 + (r-8))*NDIM + j0;
            const float* nsrc = mhc + (size_t)e*NDIM + j0;
            float sv[16];
            #pragma unroll
            for (int q2 = 0; q2 < 4; q2++) {
                float4 w = *(const float4*)(wsrc + q2*4);
                float4 n = *(const float4*)(nsrc + q2*4);
                sv[q2*4+0] = w.x*n.x; sv[q2*4+1] = w.y*n.y;
                sv[q2*4+2] = w.z*n.z; sv[q2*4+3] = w.w*n.w;
            }
            __half2 o[8]; perm16(sv, o);
            hf* q = g_phiW + l * 16;
            *(uint4*)q = *(uint4*)o;
            *(uint4*)(q + 8) = *(uint4*)(o + 4);
        }
    }
}

// ---- fp16 GEMM 128x128, 2 CTA/SM ----
// MODE 0 raw->Cf, 1 silu->Ch, 2 sigm->Cf, 5 mulAux->Cf, 6 atomicAdd->Cf (splitK x3)
template <int MODE>
__global__ void __launch_bounds__(256, 2) k_gemm(
    const hf* __restrict__ A, int lda,
    const hf* __restrict__ W, int ldw, int Ntot, int KT,
    float* __restrict__ Cf, hf* __restrict__ Ch, int ldc,
    const float* __restrict__ Aux, int ldaux, int cntOv)
{
    extern __shared__ hf smh[];
    int e = blockIdx.z;
    int kt_begin = 0, kt_end = KT;
    if (MODE == 6) {
        int per = (KT + 2) / 3;
        kt_begin = blockIdx.z * per;
        kt_end = min(KT, kt_begin + per);
        e = 0;
    }
    int cnt = (cntOv >= 0) ? cntOv : g_cnt[e];
    int m0 = blockIdx.x * 128;
    if (m0 >= cnt) return;
    int n0 = blockIdx.y * 128;

    A += (size_t)e * CAP * lda;
    W += (size_t)e * Ntot * ldw;
    size_t co = (size_t)e * CAP * ldc;
    if (Cf) Cf += co;
    if (Ch) Ch += co;
    if (Aux) Aux += (size_t)e * CAP * ldaux;

    uint32_t sb = (uint32_t)__cvta_generic_to_shared(smh);
    int tid = threadIdx.x, warp = tid >> 5, lane = tid & 31;
    int wm = warp >> 1, wn = warp & 1;
    int qr = lane >> 2, qc = lane & 3;

    float acc[2][8][4];
    #pragma unroll
    for (int mt = 0; mt < 2; mt++)
        #pragma unroll
        for (int nt = 0; nt < 8; nt++)
            #pragma unroll
            for (int q = 0; q < 4; q++) acc[mt][nt][q] = 0.f;

    auto load_stage = [&](int kt, int stg) {
        int k0 = kt * KC;
        #pragma unroll
        for (int s4 = 0; s4 < 4; s4++) {
            int f = tid + s4*256, r = f >> 3, c = f & 7;
            cp16(sb + stg*STG_B + r*160 + c*16, A + (size_t)(m0 + r)*lda + k0 + c*8, true);
        }
        #pragma unroll
        for (int s4 = 0; s4 < 4; s4++) {
            int f = tid + s4*256, r = f >> 3, c = f & 7;
            bool pr = (n0 + r) < Ntot;
            const hf* gp = W + (size_t)(n0 + r)*ldw + k0 + c*8;
            cp16(sb + stg*STG_B + 20480 + r*160 + c*16, pr ? gp : W, pr);
        }
        asm volatile("cp.async.commit_group;");
    };

    int nk = kt_end - kt_begin;
    load_stage(kt_begin, 0);

    for (int i = 0; i < nk; i++) {
        if (i + 1 < nk) load_stage(kt_begin + i + 1, (i + 1) & 1);
        if (i + 1 < nk) asm volatile("cp.async.wait_group 1;");
        else            asm volatile("cp.async.wait_group 0;");
        __syncthreads();

        int stg = i & 1;
        const hf* Asm = smh + stg * (STG_B/2);
        const hf* Bsm = Asm + 10240;

        #pragma unroll
        for (int ks = 0; ks < 4; ks++) {
            int kb = ks * 16 + qc * 4;
            uint2 a0 = *(const uint2*)(Asm + (wm*32 + qr)*RSH + kb);
            uint2 a1 = *(const uint2*)(Asm + (wm*32 + qr + 8)*RSH + kb);
            uint2 a2 = *(const uint2*)(Asm + (wm*32 + 16 + qr)*RSH + kb);
            uint2 a3 = *(const uint2*)(Asm + (wm*32 + 16 + qr + 8)*RSH + kb);
            const hf* bp = Bsm + (wn*64 + qr)*RSH + kb;
            #pragma unroll
            for (int nt = 0; nt < 8; nt++) {
                uint2 bb = *(const uint2*)(bp + nt*8*RSH);
                mma16(acc[0][nt], a0.x, a1.x, a0.y, a1.y, bb.x, bb.y);
                mma16(acc[1][nt], a2.x, a3.x, a2.y, a3.y, bb.x, bb.y);
            }
        }
        __syncthreads();
    }

    #pragma unroll
    for (int mt = 0; mt < 2; mt++) {
        #pragma unroll
        for (int nt = 0; nt < 8; nt++) {
            int n = n0 + wn*64 + nt*8 + qc*2;
            #pragma unroll
            for (int half = 0; half < 2; half++) {
                int m = m0 + wm*32 + mt*16 + qr + half*8;
                if (m >= cnt) continue;
                float v0 = acc[mt][nt][half*2], v1 = acc[mt][nt][half*2 + 1];
                if (MODE == 0) {
                    if (n < Ntot) {
                        float2 s2 = {v0, v1};
                        *(float2*)(Cf + (size_t)m * ldc + n) = s2;
                    }
                } else if (MODE == 6) {
                    if (n < Ntot) {
                        atomicAdd(Cf + (size_t)m * ldc + n, v0);
                        atomicAdd(Cf + (size_t)m * ldc + n + 1, v1);
                    }
                } else if (MODE == 2) {
                    if (n < Ntot) {
                        float2 s2 = {1.f/(1.f+expf(-v0)), 1.f/(1.f+expf(-v1))};
                        *(float2*)(Cf + (size_t)m * ldc + n) = s2;
                    }
                } else if (MODE == 5) {
                    if (n < Ntot) {
                        float2 s2 = {v0 * Aux[(size_t)m*ldaux + n], v1 * Aux[(size_t)m*ldaux + n + 1]};
                        *(float2*)(Cf + (size_t)m * ldc + n) = s2;
                    }
                } else {
                    if (n < Ntot) {
                        float x0 = v0/(1.f+expf(-v0)), x1 = v1/(1.f+expf(-v1));
                        size_t rowo = (size_t)m * ldc + (n & ~15);
                        *(__half2*)(Ch + rowo + posh(n & 15)) = __floats2half2_rn(x0, x1);
                    }
                }
            }
        }
    }
}

// ---- fused gate/up fp16 GEMM: 128x64 tile, 256 threads, 2 CTA/SM ----
__global__ void __launch_bounds__(256, 2) k_gemmF(
    const hf* __restrict__ A,
    const hf* __restrict__ Wg, const hf* __restrict__ Wu,
    hf* __restrict__ Ch)
{
    extern __shared__ hf smh[];
    int e = blockIdx.z;
    int cnt = g_cnt[e];
    int m0 = blockIdx.x * 128;
    if (m0 >= cnt) return;
    int n0 = blockIdx.y * 64;

    A  += (size_t)e * CAP * DD;
    Wg += (size_t)e * DFFN * DD;
    Wu += (size_t)e * DFFN * DD;
    Ch += (size_t)e * CAP * LDP;

    uint32_t sb = (uint32_t)__cvta_generic_to_shared(smh);
    int tid = threadIdx.x, warp = tid >> 5, lane = tid & 31;
    int wm = warp >> 2, wn = warp & 3;       // 2m x 4n warps; warp tile 64m x 16n
    int qr = lane >> 2, qc = lane & 3;

    float accG[4][2][4], accU[4][2][4];
    #pragma unroll
    for (int mt = 0; mt < 4; mt++)
        #pragma unroll
        for (int nt = 0; nt < 2; nt++)
            #pragma unroll
            for (int q = 0; q < 4; q++) { accG[mt][nt][q] = 0.f; accU[mt][nt][q] = 0.f; }

    // smem rows: [0,128) A, [128,192) Wg, [192,256) Wu
    auto load_stage = [&](int kt, int stg) {
        int k0 = kt * KC;
        #pragma unroll
        for (int i = 0; i < 8; i++) {
            int f = tid + i*256, r = f >> 3, c = f & 7;
            const hf* gp; bool pr = true;
            if (r < 128) {
                gp = A + (size_t)(m0 + r)*DD + k0 + c*8;
            } else if (r < 192) {
                int nr = n0 + r - 128; pr = nr < DFFN;
                gp = pr ? (Wg + (size_t)nr*DD + k0 + c*8) : A;
            } else {
                int nr = n0 + r - 192; pr = nr < DFFN;
                gp = pr ? (Wu + (size_t)nr*DD + k0 + c*8) : A;
            }
            cp16(sb + stg*STG_B + r*160 + c*16, gp, pr);
        }
        asm volatile("cp.async.commit_group;");
    };

    const int KT = DD / KC;
    load_stage(0, 0);

    for (int kt = 0; kt < KT; kt++) {
        if (kt + 1 < KT) load_stage(kt + 1, (kt + 1) & 1);
        if (kt + 1 < KT) asm volatile("cp.async.wait_group 1;");
        else             asm volatile("cp.async.wait_group 0;");
        __syncthreads();

        int stg = kt & 1;
        const hf* Asm = smh + stg * (STG_B/2);
        const hf* Gsm = Asm + 128*RSH;
        const hf* Usm = Asm + 192*RSH;

        #pragma unroll
        for (int ks = 0; ks < 4; ks++) {
            int kb = ks * 16 + qc * 4;
            uint2 al[4], ah[4];
            #pragma unroll
            for (int mt = 0; mt < 4; mt++) {
                al[mt] = *(const uint2*)(Asm + (wm*64 + mt*16 + qr)*RSH + kb);
                ah[mt] = *(const uint2*)(Asm + (wm*64 + mt*16 + qr + 8)*RSH + kb);
            }
            #pragma unroll
            for (int nt = 0; nt < 2; nt++) {
                int br = (wn*16 + nt*8 + qr)*RSH + kb;
                uint2 bg = *(const uint2*)(Gsm + br);
                uint2 bu = *(const uint2*)(Usm + br);
                #pragma unroll
                for (int mt = 0; mt < 4; mt++) {
                    mma16(accG[mt][nt], al[mt].x, ah[mt].x, al[mt].y, ah[mt].y, bg.x, bg.y);
                    mma16(accU[mt][nt], al[mt].x, ah[mt].x, al[mt].y, ah[mt].y, bu.x, bu.y);
                }
            }
        }
        __syncthreads();
    }

    #pragma unroll
    for (int mt = 0; mt < 4; mt++) {
        #pragma unroll
        for (int nt = 0; nt < 2; nt++) {
            int n = n0 + wn*16 + nt*8 + qc*2;
            #pragma unroll
            for (int half = 0; half < 2; half++) {
                int m = m0 + wm*64 + mt*16 + qr + half*8;
                if (m >= cnt) continue;
                size_t rowo = (size_t)m * LDP + (n & ~15);
                int p0 = posh(n & 15);
                if (n < DFFN) {
                    float gv0 = accG[mt][nt][half*2], gv1 = accG[mt][nt][half*2 + 1];
                    float uv0 = accU[mt][nt][half*2], uv1 = accU[mt][nt][half*2 + 1];
                    float x0 = (gv0/(1.f+expf(-gv0))) * uv0;
                    float x1 = (gv1/(1.f+expf(-gv1))) * uv1;
                    *(__half2*)(Ch + rowo + p0) = __floats2half2_rn(x0, x1);
                } else if (n < LDP) {
                    *(__half2*)(Ch + rowo + p0) = __floats2half2_rn(0.f, 0.f);
                }
            }
        }
    }
}

// ---- per-token: gates, sinkhorn, h, hn ----
__global__ void __launch_bounds__(128) k_hn(const float* __restrict__ stream,
                                            const float* __restrict__ b_pre,
                                            const float* __restrict__ b_post,
                                            const float* __restrict__ b_res,
                                            const float* __restrict__ alpha_pre,
                                            const float* __restrict__ alpha_post,
                                            const float* __restrict__ alpha_res,
                                            const float* __restrict__ sw_norm_w)
{
    int token = blockIdx.x, b = token / TT, t = token % TT, tid = threadIdx.x;
    __shared__ float hpre[NS], red2[4];
    int lane = tid & 31, warp = tid >> 5;

    const float* sp0 = stream + ((size_t)b*NS*TT + t) * DD;
    float st[4][8];
    #pragma unroll
    for (int i = 0; i < 4; i++)
        #pragma unroll
        for (int u = 0; u < 8; u++)
            st[i][u] = sp0[(size_t)i*TT*DD + tid + u*128];

    for (int e = 0; e < EE; e++) {
        int row = g_row[token*EE + e];
        if (row < 0) continue;
        __syncthreads();
        if (tid == 0) {
            const float* d = g_dots + (size_t)token*384 + e*24;
            size_t slot = (size_t)e*CAP + row;
            float ap = alpha_pre[e], ao = alpha_post[e], ar = alpha_res[e];
            #pragma unroll
            for (int i = 0; i < NS; i++)
                hpre[i] = 1.f / (1.f + expf(-(ap*d[i] + b_pre[e*NS+i])));
            #pragma unroll
            for (int i = 0; i < NS; i++)
                g_Hpost[slot*NS+i] = 2.f / (1.f + expf(-(ao*d[4+i] + b_post[e*NS+i])));
            float M[16];
            #pragma unroll
            for (int k = 0; k < 16; k++) M[k] = expf(ar*d[8+k] + b_res[e*16+k]);
            for (int it = 0; it < 6; it++) {
                #pragma unroll
                for (int i = 0; i < 4; i++) {
                    float ir = 1.f / (M[i*4]+M[i*4+1]+M[i*4+2]+M[i*4+3]);
                    M[i*4]*=ir; M[i*4+1]*=ir; M[i*4+2]*=ir; M[i*4+3]*=ir;
                }
                #pragma unroll
                for (int j = 0; j < 4; j++) {
                    float ic = 1.f / (M[j]+M[4+j]+M[8+j]+M[12+j]);
                    M[j]*=ic; M[4+j]*=ic; M[8+j]*=ic; M[12+j]*=ic;
                }
            }
            #pragma unroll
            for (int k = 0; k < 16; k++) g_Hres[slot*16+k] = M[k];
        }
        __syncthreads();

        float h0 = hpre[0], h1 = hpre[1], h2 = hpre[2], h3 = hpre[3];
        float hreg[8], hq = 0.f;
        #pragma unroll
        for (int u = 0; u < 8; u++) {
            float h = h0*st[0][u] + h1*st[1][u] + h2*st[2][u] + h3*st[3][u];
            hreg[u] = h; hq += h*h;
        }
        #pragma unroll
        for (int o = 16; o > 0; o >>= 1) hq += __shfl_down_sync(0xffffffffu, hq, o);
        if (lane == 0) red2[warp] = hq;
        __syncthreads();
        float sh = rsqrtf((red2[0]+red2[1]+red2[2]+red2[3]) / (float)DD + EPS_F);
        const float* snw = sw_norm_w + (size_t)e*DD;
        hf* hn = g_HN + ((size_t)e*CAP + row) * DD;
        #pragma unroll
        for (int u = 0; u < 8; u++) {
            int dd = tid + u*128;
            float v = hreg[u] * sh * snw[dd];
            hn[(dd & ~15) + posh(dd & 15)] = __float2half_rn(v);
        }
    }
}

// ---- combine res + post ----
__global__ void __launch_bounds__(128) k_out(const float* __restrict__ stream,
                                             float* __restrict__ outp)
{
    int token = blockIdx.x, b = token / TT, t = token % TT, tid = threadIdx.x;
    const float* sp0 = stream + ((size_t)b*NS*TT + t) * DD;
    float st[4][8], acc[4][8];
    #pragma unroll
    for (int i = 0; i < 4; i++)
        #pragma unroll
        for (int j = 0; j < 8; j++) {
            st[i][j] = sp0[(size_t)i*TT*DD + tid + j*128];
            acc[i][j] = 0.f;
        }
    for (int e = 0; e < EE; e++) {
        int row = g_row[token*EE + e];
        if (row < 0) continue;
        float g = g_gatev[token*EE + e];
        size_t slot = (size_t)e*CAP + row;
        float Hr[16], Hp[4];
        #pragma unroll
        for (int k = 0; k < 16; k++) Hr[k] = g_Hres[slot*16+k];
        #pragma unroll
        for (int i = 0; i < 4; i++) Hp[i] = g_Hpost[slot*4+i];
        const float* o = g_OUT + slot*DD;
        #pragma unroll
        for (int j = 0; j < 8; j++) {
            float ov = o[tid + j*128];
            #pragma unroll
            for (int i = 0; i < 4; i++) {
                float r = Hr[i*4]*st[0][j] + Hr[i*4+1]*st[1][j]
                        + Hr[i*4+2]*st[2][j] + Hr[i*4+3]*st[3][j];
                acc[i][j] += g * (r + Hp[i]*ov);
            }
        }
    }
    #pragma unroll
    for (int i = 0; i < 4; i++)
        #pragma unroll
        for (int j = 0; j < 8; j++)
            outp[((size_t)(b*NS+i)*TT + t)*DD + tid + j*128] = acc[i][j];
}

#define GSA(p, s) cudaGetSymbolAddress((void**)&p, s)

extern "C" void kernel_launch(void* const* d_in, const int* in_sizes, int n_in,
                              void* d_out, int out_size)
{
    (void)in_sizes; (void)n_in; (void)out_size;
    const float* stream   = (const float*)d_in[0];
    const float* router_w = (const float*)d_in[1];
    const float* mhc      = (const float*)d_in[2];
    const float* phi_pre  = (const float*)d_in[3];
    const float* phi_post = (const float*)d_in[4];
    const float* phi_res  = (const float*)d_in[5];
    const float* b_pre    = (const float*)d_in[6];
    const float* b_post   = (const float*)d_in[7];
    const float* b_res    = (const float*)d_in[8];
    const float* a_pre    = (const float*)d_in[9];
    const float* a_post   = (const float*)d_in[10];
    const float* a_res    = (const float*)d_in[11];
    const float* sw_nw    = (const float*)d_in[12];
    const float* wd_w     = (const float*)d_in[13];
    const float* wu_w     = (const float*)d_in[14];
    const float* gate_w   = (const float*)d_in[15];
    const float* up_w     = (const float*)d_in[16];
    const float* down_w   = (const float*)d_in[17];

    float* outp = (float*)d_out;
    float* out_gate = outp + (size_t)BB*NS*TT*DD;

    cudaFuncSetAttribute(k_gemm<1>, cudaFuncAttributeMaxDynamicSharedMemorySize, SMEM_DYN);
    cudaFuncSetAttribute(k_gemm<2>, cudaFuncAttributeMaxDynamicSharedMemorySize, SMEM_DYN);
    cudaFuncSetAttribute(k_gemm<5>, cudaFuncAttributeMaxDynamicSharedMemorySize, SMEM_DYN);
    cudaFuncSetAttribute(k_gemm<6>, cudaFuncAttributeMaxDynamicSharedMemorySize, SMEM_DYN);
    cudaFuncSetAttribute(k_gemmF, cudaFuncAttributeMaxDynamicSharedMemorySize, SMEM_F);

    hf *base, *HN, *T1, *P2, *phiW, *gt, *up, *dn, *wd, *wu;
    float *GS, *OUT, *dots;
    GSA(base, g_base); GSA(HN, g_HN); GSA(T1, g_T1); GSA(P2, g_P2);
    GSA(phiW, g_phiW); GSA(wd, g_wd); GSA(wu, g_wu); GSA(gt, g_gt);
    GSA(up, g_up); GSA(dn, g_dn);
    GSA(GS, g_GS); GSA(OUT, g_OUT); GSA(dots, g_dots);

    k_zero<<<1, 32>>>();
    k_zdots<<<(BT*384/4)/256, 256>>>();
    k_gate<<<BT, 256>>>(stream, router_w, out_gate);
    k_packall<<<4096, 256>>>(wd_w, wu_w, gate_w, up_w, down_w,
                             mhc, phi_pre, phi_post, phi_res);

    // dots = base @ phiW^T  (N=384, K=4096), split-K x3
    k_gemm<6><<<dim3(32,3,3), 256, SMEM_DYN>>>(base, NDIM, phiW, NDIM, 384, NDIM/KC,
                                               dots, (hf*)0, 384, (const float*)0, 0, BT);

    k_hn<<<BT, 128>>>(stream, b_pre, b_post, b_res, a_pre, a_post, a_res, sw_nw);

    dim3 gD(32, 8, EE);

    // T1 = silu(HN @ wd^T) -> interleaved half
    k_gemm<1><<<gD, 256, SMEM_DYN>>>(HN, DD, wd, DD, DD, DD/KC,
                                     (float*)0, T1, DD, (const float*)0, 0, -1);
    // GS = sigmoid(T1 @ wu^T) -> f32
    k_gemm<2><<<gD, 256, SMEM_DYN>>>(T1, DD, wu, DD, DD, DD/KC,
                                     GS, (hf*)0, DD, (const float*)0, 0, -1);
    // P2 = silu(HN @ gt^T) * (HN @ up^T) -> interleaved half (128x64 tiles, 2 CTA/SM)
    k_gemmF<<<dim3(32,26,EE), 256, SMEM_F>>>(HN, gt, up, P2);
    // OUT = (P2 @ dn^T) * GS -> f32
    k_gemm<5><<<gD, 256, SMEM_DYN>>>(P2, LDP, dn, LDP, DD, LDP/KC,
                                     OUT, (hf*)0, DD, GS, DD, -1);

    k_out<<<BT, 128>>>(stream, outp);
}